// round 10
// baseline (speedup 1.0000x reference)
#include <cuda_runtime.h>

#define T_ 8
#define B_ 4
#define C_ 128
#define HW_ 9216      // 96*96
#define HW4_ 2304     // HW_/4
#define NMAP 36       // T*B + B maps to resize
#define NTB 32        // T*B
#define GRID_ 576     // 9 px-tiles * 16 c-chunks * 4 b
#define NSLOT 144     // partial slots per tb: 9 px * 16 c-chunks
#define NPV 9         // vsum partials per tb

// scratch (static __device__ — no allocation)
__device__ float g_tv[B_ * HW_];
__device__ float g_rv[NTB * HW_];
__device__ float g_pgs[NTB * NSLOT];
__device__ float g_pvs[NTB * NPV];
__device__ unsigned int g_bar = 0;   // cumulative ticket barrier (never reset)

// ---------------------------------------------------------------------------
// 1) antialiased (jax-style) 384->96 resize + threshold > 0.5
// ---------------------------------------------------------------------------
__global__ void resize_kernel(const float* __restrict__ tvmap,
                              const float* __restrict__ rvmaps) {
    int idx = blockIdx.x * blockDim.x + threadIdx.x;
    if (idx >= NMAP * HW_) return;
    int m = idx / HW_;
    int p = idx - m * HW_;
    int oy = p / 96, ox = p - oy * 96;

    const float* src = (m < B_) ? (tvmap + (size_t)m * 147456)
                                : (rvmaps + (size_t)(m - B_) * 147456);

    const float wtab[8] = {1.f, 3.f, 5.f, 7.f, 7.f, 5.f, 3.f, 1.f};
    int iy0 = 4 * oy - 2, ix0 = 4 * ox - 2;

    float wx[8];
    float wxs = 0.f;
#pragma unroll
    for (int k = 0; k < 8; k++) {
        int ix = ix0 + k;
        wx[k] = (ix >= 0 && ix < 384) ? wtab[k] : 0.f;
        wxs += wx[k];
    }

    float acc = 0.f, wys = 0.f;
#pragma unroll
    for (int ky = 0; ky < 8; ky++) {
        int iy = iy0 + ky;
        if (iy < 0 || iy >= 384) continue;
        wys += wtab[ky];
        const float* row = src + iy * 384;
        float ra = 0.f;
#pragma unroll
        for (int kx = 0; kx < 8; kx++) {
            if (wx[kx] != 0.f) ra += wx[kx] * __ldcs(row + ix0 + kx);
        }
        acc += wtab[ky] * ra;
    }
    float val = acc / (wys * wxs);
    float bin = (val > 0.5f) ? 1.f : 0.f;
    if (m < B_) g_tv[m * HW_ + p] = bin;
    else        g_rv[(m - B_) * HW_ + p] = bin;
}

// ---------------------------------------------------------------------------
// 2) FUSED persistent kernel with DETERMINISTIC L2 partitioning:
//    phase A keeps channels c%8<6 of r_feats resident (113MB < 126MB L2),
//    streams the rest evict-first; phase B hits the resident 75% exactly.
//    grid = (9 px, 16 c-chunks of 8, 4 b) = 576 blocks, 4/SM co-resident.
// ---------------------------------------------------------------------------
__global__ void __launch_bounds__(256, 4) fused_kernel(const float* __restrict__ values,
                                                       float* __restrict__ d_out) {
    int px = blockIdx.x;
    int chunk = blockIdx.y;
    int b = blockIdx.z;
    int c0 = chunk * 8;
    int tid = threadIdx.x;
    int i4 = px * 256 + tid;          // 0..2303

    const float4* vals4 = (const float4*)values;
    const float4* tf = vals4 + ((size_t)b * C_ + c0) * HW4_ + i4;
    float4* outp = (float4*)d_out + ((size_t)b * 257 + c0) * HW4_ + i4;
    const size_t tstride = (size_t)B_ * C_ * HW4_;

    float4 tv = ((const float4*)g_tv)[b * HW4_ + i4];

    __shared__ float sg[8][4], sv[8][4];
    int lane = tid & 31, w = tid >> 5;

    // ================= phase A: masked correlation partials =================
#pragma unroll
    for (int h = 0; h < 2; h++) {     // t halves: [0,4) and [4,8)
        const float4* rf = vals4 + ((size_t)(B_ + h * 4 * B_ + b) * C_ + c0) * HW4_ + i4;

        float4 acc[4];
#pragma unroll
        for (int t = 0; t < 4; t++) acc[t] = make_float4(0.f, 0.f, 0.f, 0.f);

#pragma unroll
        for (int c = 0; c < 8; c++) {
            float4 a = __ldcs(tf + c * HW4_);            // no L2 pollution
            if (h == 0) __stcs(&outp[c * HW4_], a);      // t_feat passthrough
#pragma unroll
            for (int t = 0; t < 4; t++) {
                // channels 0..5 of each chunk stay L2-resident for phase B;
                // channels 6..7 stream evict-first (budget: 6/8*151MB = 113MB)
                float4 r = (c < 6) ? __ldcg(rf + t * tstride + c * HW4_)
                                   : __ldcs(rf + t * tstride + c * HW4_);
                acc[t].x += a.x * r.x; acc[t].y += a.y * r.y;
                acc[t].z += a.z * r.z; acc[t].w += a.w * r.w;
            }
        }

        float lg[4], lv[4];
#pragma unroll
        for (int t = 0; t < 4; t++) {
            float4 rv = __ldg((const float4*)g_rv + ((h * 4 + t) * B_ + b) * HW4_ + i4);
            float m0 = tv.x * rv.x, m1 = tv.y * rv.y, m2 = tv.z * rv.z, m3 = tv.w * rv.w;
            lg[t] = acc[t].x * m0 + acc[t].y * m1 + acc[t].z * m2 + acc[t].w * m3;
            lv[t] = m0 + m1 + m2 + m3;
        }
#pragma unroll
        for (int o = 16; o > 0; o >>= 1) {
#pragma unroll
            for (int t = 0; t < 4; t++) {
                lg[t] += __shfl_down_sync(0xffffffffu, lg[t], o);
                lv[t] += __shfl_down_sync(0xffffffffu, lv[t], o);
            }
        }
        if (lane == 0) {
#pragma unroll
            for (int t = 0; t < 4; t++) { sg[w][t] = lg[t]; sv[w][t] = lv[t]; }
        }
        __syncthreads();
        if (tid < 4) {
            int t = h * 4 + tid;
            int tb = t * B_ + b;
            float a = 0.f, v = 0.f;
#pragma unroll
            for (int i = 0; i < 8; i++) { a += sg[i][tid]; v += sv[i][tid]; }
            g_pgs[tb * NSLOT + px * 16 + chunk] = a;
            if (chunk == 0) g_pvs[tb * NPV + px] = v;
        }
        __syncthreads();
    }

    // ===================== software grid barrier =====================
    __threadfence();
    if (tid == 0) {
        unsigned int ticket = atomicAdd(&g_bar, 1u);
        unsigned int target = (ticket / GRID_ + 1u) * GRID_;
        while (*((volatile unsigned int*)&g_bar) < target) __nanosleep(64);
    }
    __syncthreads();
    __threadfence();

    // ============== phase B: gs finalize + match + aggregate ==============
    __shared__ float sE[T_];
    if (tid < 128) {
        int t = tid >> 4, j = tid & 15;
        int tb = t * B_ + b;
        float s = 0.f;
#pragma unroll
        for (int k = 0; k < 9; k++) s += g_pgs[tb * NSLOT + k * 16 + j];
#pragma unroll
        for (int o = 8; o > 0; o >>= 1)
            s += __shfl_down_sync(0xffffffffu, s, o, 16);
        if (j == 0) {
            float vs = 0.f;
#pragma unroll
            for (int k = 0; k < NPV; k++) vs += g_pvs[tb * NPV + k];
            float g = (vs < 1e-4f) ? 0.f : (s / vs) * (1.f / 128.f);
            sE[t] = expf(g);
            if (px == 0 && chunk == 0)
                d_out[(size_t)B_ * 257 * HW_ + (size_t)B_ * HW_ + tb] = g;
        }
    }
    __syncthreads();

    const float4* rvp = (const float4*)g_rv + (size_t)b * HW4_ + i4;
    const size_t rvstride = (size_t)B_ * HW4_;

    float4 ms = make_float4(0.f, 0.f, 0.f, 0.f);
    float4 inv;
#pragma unroll
    for (int grp = 0; grp < 2; grp++) {   // two 4-channel groups of this chunk
        int cc0 = c0 + grp * 4;
        const float4* rfb = vals4 + ((size_t)(B_ + b) * C_ + cc0) * HW4_ + i4;

        float4 acc0 = make_float4(0.f, 0.f, 0.f, 0.f);
        float4 acc1 = acc0, acc2 = acc0, acc3 = acc0;
#pragma unroll
        for (int t = 0; t < T_; t++) {
            float4 rv = __ldg(rvp + t * rvstride);
            float e = sE[t];
            float4 w4 = make_float4(rv.x * e, rv.y * e, rv.z * e, rv.w * e);
            if (grp == 0) { ms.x += w4.x; ms.y += w4.y; ms.z += w4.z; ms.w += w4.w; }
            float4 r0 = __ldcs(rfb + t * tstride + 0 * HW4_);   // hit (resident)
            float4 r1 = __ldcs(rfb + t * tstride + 1 * HW4_);   // hit (resident)
            float4 r2 = __ldcs(rfb + t * tstride + 2 * HW4_);   // grp0: hit; grp1: miss
            float4 r3 = __ldcs(rfb + t * tstride + 3 * HW4_);   // grp0: hit; grp1: miss
            acc0.x += r0.x * w4.x; acc0.y += r0.y * w4.y; acc0.z += r0.z * w4.z; acc0.w += r0.w * w4.w;
            acc1.x += r1.x * w4.x; acc1.y += r1.y * w4.y; acc1.z += r1.z * w4.z; acc1.w += r1.w * w4.w;
            acc2.x += r2.x * w4.x; acc2.y += r2.y * w4.y; acc2.z += r2.z * w4.z; acc2.w += r2.w * w4.w;
            acc3.x += r3.x * w4.x; acc3.y += r3.y * w4.y; acc3.z += r3.z * w4.z; acc3.w += r3.w * w4.w;
        }

        if (grp == 0) {
            inv.x = 1.f / (ms.x + ((ms.x < 1e-4f) ? 1.f : 0.f));
            inv.y = 1.f / (ms.y + ((ms.y < 1e-4f) ? 1.f : 0.f));
            inv.z = 1.f / (ms.z + ((ms.z < 1e-4f) ? 1.f : 0.f));
            inv.w = 1.f / (ms.w + ((ms.w < 1e-4f) ? 1.f : 0.f));
            if (chunk == 0) {   // c_mask written once per pixel
                float4 msk = make_float4(1.f - ms.x * inv.x, 1.f - ms.y * inv.y,
                                         1.f - ms.z * inv.z, 1.f - ms.w * inv.w);
                float4* op = (float4*)d_out;
                __stcs(&op[((size_t)b * 257 + 256) * HW4_ + i4], msk);
                __stcs(&op[(size_t)B_ * 257 * HW4_ + (size_t)b * HW4_ + i4], msk);
            }
        }

        acc0.x *= inv.x; acc0.y *= inv.y; acc0.z *= inv.z; acc0.w *= inv.w;
        acc1.x *= inv.x; acc1.y *= inv.y; acc1.z *= inv.z; acc1.w *= inv.w;
        acc2.x *= inv.x; acc2.y *= inv.y; acc2.z *= inv.z; acc2.w *= inv.w;
        acc3.x *= inv.x; acc3.y *= inv.y; acc3.z *= inv.z; acc3.w *= inv.w;

        float4* outc = (float4*)d_out + ((size_t)b * 257 + 128 + cc0) * HW4_ + i4;
        __stcs(&outc[0 * HW4_], acc0);
        __stcs(&outc[1 * HW4_], acc1);
        __stcs(&outc[2 * HW4_], acc2);
        __stcs(&outc[3 * HW4_], acc3);
    }
}

// ---------------------------------------------------------------------------
extern "C" void kernel_launch(void* const* d_in, const int* in_sizes, int n_in,
                              void* d_out, int out_size) {
    const float* values = (const float*)d_in[0];   // (9,4,128,96,96)
    const float* tvmap  = (const float*)d_in[1];   // (4,1,384,384)
    const float* rvmaps = (const float*)d_in[2];   // (8,4,1,384,384)
    float* out = (float*)d_out;

    resize_kernel<<<(NMAP * HW_ + 255) / 256, 256>>>(tvmap, rvmaps);

    dim3 gf(9, 16, B_);
    fused_kernel<<<gf, 256>>>(values, out);
}

// round 11
// speedup vs baseline: 1.2230x; 1.2230x over previous
#include <cuda_runtime.h>

#define T_ 8
#define B_ 4
#define C_ 128
#define HW_ 9216      // 96*96
#define HW4_ 2304     // HW_/4
#define NMAP 36       // T*B + B maps to resize
#define NTB 32        // T*B
#define GRID_ 576     // 9 px-tiles * 16 c-chunks * 4 b
#define NSLOT 144     // partial slots per tb: 9 px * 16 c-chunks
#define NPV 9         // vsum partials per tb

// scratch (static __device__ — no allocation)
__device__ float g_tv[B_ * HW_];
__device__ float g_rv[NTB * HW_];
__device__ float g_pgs[NTB * NSLOT];
__device__ float g_pvs[NTB * NPV];
__device__ unsigned int g_bar = 0;   // cumulative ticket barrier (never reset)

__device__ __forceinline__ void grid_barrier(int tid) {
    __threadfence();
    __syncthreads();
    if (tid == 0) {
        unsigned int ticket = atomicAdd(&g_bar, 1u);
        unsigned int target = (ticket / GRID_ + 1u) * GRID_;
        while (*((volatile unsigned int*)&g_bar) < target) __nanosleep(64);
    }
    __syncthreads();
    __threadfence();
}

// ---------------------------------------------------------------------------
// SINGLE persistent kernel:
//   phase 0: antialiased 384->96 resize + threshold (vectorized, all blocks)
//   barrier
//   phase A: masked correlation partials + t_feat passthrough
//   barrier
//   phase B: gs finalize + match + aggregate (reverse-order slab re-read)
// grid = (9 px, 16 c-chunks of 8, 4 b) = 576 blocks; launch_bounds(256,4)
// guarantees 592 co-resident slots >= 576 (no barrier deadlock).
// ---------------------------------------------------------------------------
__global__ void __launch_bounds__(256, 4) fused_kernel(const float* __restrict__ values,
                                                       const float* __restrict__ tvmap,
                                                       const float* __restrict__ rvmaps,
                                                       float* __restrict__ d_out) {
    int px = blockIdx.x;
    int chunk = blockIdx.y;
    int b = blockIdx.z;
    int c0 = chunk * 8;
    int tid = threadIdx.x;
    int i4 = px * 256 + tid;          // 0..2303

    // ================= phase 0: resize (work-distributed) =================
    {
        int bid = blockIdx.x + 9 * (blockIdx.y + 16 * blockIdx.z);
        const float wtab[8] = {1.f, 3.f, 5.f, 7.f, 7.f, 5.f, 3.f, 1.f};
#pragma unroll
        for (int it = 0; it < 3; it++) {
            int idx = bid * 256 + tid + it * (GRID_ * 256);
            if (idx >= NMAP * HW_) break;
            int m = idx / HW_;
            int p = idx - m * HW_;
            int oy = p / 96, ox = p - oy * 96;

            const float* src = (m < B_) ? (tvmap + (size_t)m * 147456)
                                        : (rvmaps + (size_t)(m - B_) * 147456);
            int iy0 = 4 * oy - 2;
            int xbase = 4 * ox - 4;               // float4-aligned window start
            bool has0 = (ox > 0), has2 = (ox < 95);
            float wxs = 32.f - (has0 ? 0.f : 4.f) - (has2 ? 0.f : 4.f);

            float acc = 0.f, wys = 0.f;
#pragma unroll
            for (int ky = 0; ky < 8; ky++) {
                int iy = iy0 + ky;
                if (iy < 0 || iy >= 384) continue;
                wys += wtab[ky];
                const float4* rp = (const float4*)(src + iy * 384 + xbase);
                float4 b0 = has0 ? __ldg(rp)     : make_float4(0.f, 0.f, 0.f, 0.f);
                float4 b1 = __ldg(rp + 1);
                float4 b2 = has2 ? __ldg(rp + 2) : make_float4(0.f, 0.f, 0.f, 0.f);
                float ra = b0.z + 3.f * b0.w
                         + 5.f * b1.x + 7.f * (b1.y + b1.z) + 5.f * b1.w
                         + 3.f * b2.x + b2.y;
                acc += wtab[ky] * ra;
            }
            float val = acc / (wys * wxs);
            float bin = (val > 0.5f) ? 1.f : 0.f;
            if (m < B_) g_tv[m * HW_ + p] = bin;
            else        g_rv[(m - B_) * HW_ + p] = bin;
        }
    }

    grid_barrier(tid);

    // ================= phase A: masked correlation partials =================
    const float4* vals4 = (const float4*)values;
    const float4* tf = vals4 + ((size_t)b * C_ + c0) * HW4_ + i4;
    float4* outp = (float4*)d_out + ((size_t)b * 257 + c0) * HW4_ + i4;
    const size_t tstride = (size_t)B_ * C_ * HW4_;

    float4 tv = ((const float4*)g_tv)[b * HW4_ + i4];

    __shared__ float sg[8][4], sv[8][4];
    int lane = tid & 31, w = tid >> 5;

#pragma unroll
    for (int h = 0; h < 2; h++) {     // t halves: [0,4) and [4,8)
        const float4* rf = vals4 + ((size_t)(B_ + h * 4 * B_ + b) * C_ + c0) * HW4_ + i4;

        float4 acc[4];
#pragma unroll
        for (int t = 0; t < 4; t++) acc[t] = make_float4(0.f, 0.f, 0.f, 0.f);

#pragma unroll
        for (int c = 0; c < 8; c++) {
            float4 a = __ldg(tf + c * HW4_);             // L1-resident on 2nd half
            if (h == 0) __stcs(&outp[c * HW4_], a);      // t_feat passthrough
#pragma unroll
            for (int t = 0; t < 4; t++) {
                float4 r = __ldcg(rf + t * tstride + c * HW4_);  // L2 fill, skip L1
                acc[t].x += a.x * r.x; acc[t].y += a.y * r.y;
                acc[t].z += a.z * r.z; acc[t].w += a.w * r.w;
            }
        }

        float lg[4], lv[4];
#pragma unroll
        for (int t = 0; t < 4; t++) {
            float4 rv = __ldg((const float4*)g_rv + ((h * 4 + t) * B_ + b) * HW4_ + i4);
            float m0 = tv.x * rv.x, m1 = tv.y * rv.y, m2 = tv.z * rv.z, m3 = tv.w * rv.w;
            lg[t] = acc[t].x * m0 + acc[t].y * m1 + acc[t].z * m2 + acc[t].w * m3;
            lv[t] = m0 + m1 + m2 + m3;
        }
#pragma unroll
        for (int o = 16; o > 0; o >>= 1) {
#pragma unroll
            for (int t = 0; t < 4; t++) {
                lg[t] += __shfl_down_sync(0xffffffffu, lg[t], o);
                lv[t] += __shfl_down_sync(0xffffffffu, lv[t], o);
            }
        }
        if (lane == 0) {
#pragma unroll
            for (int t = 0; t < 4; t++) { sg[w][t] = lg[t]; sv[w][t] = lv[t]; }
        }
        __syncthreads();
        if (tid < 4) {
            int t = h * 4 + tid;
            int tb = t * B_ + b;
            float a = 0.f, v = 0.f;
#pragma unroll
            for (int i = 0; i < 8; i++) { a += sg[i][tid]; v += sv[i][tid]; }
            g_pgs[tb * NSLOT + px * 16 + chunk] = a;
            if (chunk == 0) g_pvs[tb * NPV + px] = v;
        }
        __syncthreads();
    }

    grid_barrier(tid);

    // ============== phase B: gs finalize + match + aggregate ==============
    __shared__ float sE[T_];
    if (tid < 128) {
        int t = tid >> 4, j = tid & 15;
        int tb = t * B_ + b;
        float s = 0.f;
#pragma unroll
        for (int k = 0; k < 9; k++) s += g_pgs[tb * NSLOT + k * 16 + j];
#pragma unroll
        for (int o = 8; o > 0; o >>= 1)
            s += __shfl_down_sync(0xffffffffu, s, o, 16);
        if (j == 0) {
            float vs = 0.f;
#pragma unroll
            for (int k = 0; k < NPV; k++) vs += g_pvs[tb * NPV + k];
            float g = (vs < 1e-4f) ? 0.f : (s / vs) * (1.f / 128.f);
            sE[t] = expf(g);
            if (px == 0 && chunk == 0)
                d_out[(size_t)B_ * 257 * HW_ + (size_t)B_ * HW_ + tb] = g;
        }
    }
    __syncthreads();

    const float4* rvp = (const float4*)g_rv + (size_t)b * HW4_ + i4;
    const size_t rvstride = (size_t)B_ * HW4_;

    float4 ms = make_float4(0.f, 0.f, 0.f, 0.f);
    float4 inv;
#pragma unroll
    for (int gi = 0; gi < 2; gi++) {      // reverse of phase-A order: grp1 first
        int grp = 1 - gi;
        int cc0 = c0 + grp * 4;
        const float4* rfb = vals4 + ((size_t)(B_ + b) * C_ + cc0) * HW4_ + i4;

        float4 acc0 = make_float4(0.f, 0.f, 0.f, 0.f);
        float4 acc1 = acc0, acc2 = acc0, acc3 = acc0;
#pragma unroll
        for (int t = T_ - 1; t >= 0; t--) {   // newest L2 lines first
            float4 rv = __ldg(rvp + t * rvstride);
            float e = sE[t];
            float4 w4 = make_float4(rv.x * e, rv.y * e, rv.z * e, rv.w * e);
            if (gi == 0) { ms.x += w4.x; ms.y += w4.y; ms.z += w4.z; ms.w += w4.w; }
            float4 r0 = __ldcs(rfb + t * tstride + 0 * HW4_);
            float4 r1 = __ldcs(rfb + t * tstride + 1 * HW4_);
            float4 r2 = __ldcs(rfb + t * tstride + 2 * HW4_);
            float4 r3 = __ldcs(rfb + t * tstride + 3 * HW4_);
            acc0.x += r0.x * w4.x; acc0.y += r0.y * w4.y; acc0.z += r0.z * w4.z; acc0.w += r0.w * w4.w;
            acc1.x += r1.x * w4.x; acc1.y += r1.y * w4.y; acc1.z += r1.z * w4.z; acc1.w += r1.w * w4.w;
            acc2.x += r2.x * w4.x; acc2.y += r2.y * w4.y; acc2.z += r2.z * w4.z; acc2.w += r2.w * w4.w;
            acc3.x += r3.x * w4.x; acc3.y += r3.y * w4.y; acc3.z += r3.z * w4.z; acc3.w += r3.w * w4.w;
        }

        if (gi == 0) {
            inv.x = 1.f / (ms.x + ((ms.x < 1e-4f) ? 1.f : 0.f));
            inv.y = 1.f / (ms.y + ((ms.y < 1e-4f) ? 1.f : 0.f));
            inv.z = 1.f / (ms.z + ((ms.z < 1e-4f) ? 1.f : 0.f));
            inv.w = 1.f / (ms.w + ((ms.w < 1e-4f) ? 1.f : 0.f));
            if (chunk == 0) {   // c_mask written once per pixel
                float4 msk = make_float4(1.f - ms.x * inv.x, 1.f - ms.y * inv.y,
                                         1.f - ms.z * inv.z, 1.f - ms.w * inv.w);
                float4* op = (float4*)d_out;
                __stcs(&op[((size_t)b * 257 + 256) * HW4_ + i4], msk);
                __stcs(&op[(size_t)B_ * 257 * HW4_ + (size_t)b * HW4_ + i4], msk);
            }
        }

        acc0.x *= inv.x; acc0.y *= inv.y; acc0.z *= inv.z; acc0.w *= inv.w;
        acc1.x *= inv.x; acc1.y *= inv.y; acc1.z *= inv.z; acc1.w *= inv.w;
        acc2.x *= inv.x; acc2.y *= inv.y; acc2.z *= inv.z; acc2.w *= inv.w;
        acc3.x *= inv.x; acc3.y *= inv.y; acc3.z *= inv.z; acc3.w *= inv.w;

        float4* outc = (float4*)d_out + ((size_t)b * 257 + 128 + cc0) * HW4_ + i4;
        __stcs(&outc[0 * HW4_], acc0);
        __stcs(&outc[1 * HW4_], acc1);
        __stcs(&outc[2 * HW4_], acc2);
        __stcs(&outc[3 * HW4_], acc3);
    }
}

// ---------------------------------------------------------------------------
extern "C" void kernel_launch(void* const* d_in, const int* in_sizes, int n_in,
                              void* d_out, int out_size) {
    const float* values = (const float*)d_in[0];   // (9,4,128,96,96)
    const float* tvmap  = (const float*)d_in[1];   // (4,1,384,384)
    const float* rvmaps = (const float*)d_in[2];   // (8,4,1,384,384)
    float* out = (float*)d_out;

    dim3 gf(9, 16, B_);
    fused_kernel<<<gf, 256>>>(values, tvmap, rvmaps, out);
}

// round 12
// speedup vs baseline: 1.2562x; 1.0272x over previous
#include <cuda_runtime.h>

#define T_ 8
#define B_ 4
#define C_ 128
#define HW_ 9216      // 96*96
#define HW4_ 2304     // HW_/4
#define NMAP 36       // T*B + B maps to resize
#define NTB 32        // T*B
#define GRID_ 576     // 9 px-tiles * 16 c-chunks * 4 b
#define NSLOT 144     // partial slots per tb: 9 px * 16 c-chunks
#define NPV 9         // vsum partials per tb

// scratch (static __device__ — no allocation)
__device__ float g_tv[B_ * HW_];
__device__ float g_rv[NTB * HW_];
__device__ float g_pgs[NTB * NSLOT];
__device__ float g_pvs[NTB * NPV];
__device__ unsigned int g_bar = 0;   // cumulative ticket barrier (never reset)

__device__ __forceinline__ void grid_barrier(int tid) {
    __threadfence();
    __syncthreads();
    if (tid == 0) {
        unsigned int ticket = atomicAdd(&g_bar, 1u);
        unsigned int target = (ticket / GRID_ + 1u) * GRID_;
        while (*((volatile unsigned int*)&g_bar) < target) __nanosleep(64);
    }
    __syncthreads();
    __threadfence();
}

// ---------------------------------------------------------------------------
// SINGLE persistent kernel, barrier moved to hide resize latency:
//   phase 0: resize (vectorized)          [no barrier yet]
//   h=0 c-loop (16 us of streaming — hides resize skew)
//   BARRIER 1 (orders resize writes vs mask reads)
//   h=0 mask+partials, h=1 c-loop, h=1 mask+partials
//   BARRIER 2
//   phase B: gs finalize + match + aggregate
// ---------------------------------------------------------------------------
__global__ void __launch_bounds__(256, 4) fused_kernel(const float* __restrict__ values,
                                                       const float* __restrict__ tvmap,
                                                       const float* __restrict__ rvmaps,
                                                       float* __restrict__ d_out) {
    int px = blockIdx.x;
    int chunk = blockIdx.y;
    int b = blockIdx.z;
    int c0 = chunk * 8;
    int tid = threadIdx.x;
    int i4 = px * 256 + tid;          // 0..2303

    // ================= phase 0: resize (work-distributed) =================
    {
        int bid = blockIdx.x + 9 * (blockIdx.y + 16 * blockIdx.z);
        const float wtab[8] = {1.f, 3.f, 5.f, 7.f, 7.f, 5.f, 3.f, 1.f};
#pragma unroll
        for (int it = 0; it < 3; it++) {
            int idx = bid * 256 + tid + it * (GRID_ * 256);
            if (idx >= NMAP * HW_) break;
            int m = idx / HW_;
            int p = idx - m * HW_;
            int oy = p / 96, ox = p - oy * 96;

            const float* src = (m < B_) ? (tvmap + (size_t)m * 147456)
                                        : (rvmaps + (size_t)(m - B_) * 147456);
            int iy0 = 4 * oy - 2;
            int xbase = 4 * ox - 4;               // float4-aligned window start
            bool has0 = (ox > 0), has2 = (ox < 95);
            float wxs = 32.f - (has0 ? 0.f : 4.f) - (has2 ? 0.f : 4.f);

            float acc = 0.f, wys = 0.f;
#pragma unroll
            for (int ky = 0; ky < 8; ky++) {
                int iy = iy0 + ky;
                if (iy < 0 || iy >= 384) continue;
                wys += wtab[ky];
                const float4* rp = (const float4*)(src + iy * 384 + xbase);
                float4 b0 = has0 ? __ldg(rp)     : make_float4(0.f, 0.f, 0.f, 0.f);
                float4 b1 = __ldg(rp + 1);
                float4 b2 = has2 ? __ldg(rp + 2) : make_float4(0.f, 0.f, 0.f, 0.f);
                float ra = b0.z + 3.f * b0.w
                         + 5.f * b1.x + 7.f * (b1.y + b1.z) + 5.f * b1.w
                         + 3.f * b2.x + b2.y;
                acc += wtab[ky] * ra;
            }
            float val = acc / (wys * wxs);
            float bin = (val > 0.5f) ? 1.f : 0.f;
            if (m < B_) g_tv[m * HW_ + p] = bin;
            else        g_rv[(m - B_) * HW_ + p] = bin;
        }
    }

    // ============ phase A, half h=0: c-loop (masks NOT needed yet) ==========
    const float4* vals4 = (const float4*)values;
    const float4* tf = vals4 + ((size_t)b * C_ + c0) * HW4_ + i4;
    float4* outp = (float4*)d_out + ((size_t)b * 257 + c0) * HW4_ + i4;
    const size_t tstride = (size_t)B_ * C_ * HW4_;

    __shared__ float sg[8][4], sv[8][4];
    int lane = tid & 31, w = tid >> 5;

    float4 acc0[4];
#pragma unroll
    for (int t = 0; t < 4; t++) acc0[t] = make_float4(0.f, 0.f, 0.f, 0.f);
    {
        const float4* rf = vals4 + ((size_t)(B_ + b) * C_ + c0) * HW4_ + i4;
#pragma unroll
        for (int c = 0; c < 8; c++) {
            float4 a = __ldg(tf + c * HW4_);
            __stcs(&outp[c * HW4_], a);              // t_feat passthrough
#pragma unroll
            for (int t = 0; t < 4; t++) {
                float4 r = __ldcg(rf + t * tstride + c * HW4_);
                acc0[t].x += a.x * r.x; acc0[t].y += a.y * r.y;
                acc0[t].z += a.z * r.z; acc0[t].w += a.w * r.w;
            }
        }
    }

    // barrier 1: resize writes (all blocks) -> mask reads; hidden behind c-loop
    grid_barrier(tid);

    float4 tv = ((const float4*)g_tv)[b * HW4_ + i4];

    // ---- h=0 mask application + partial reduction ----
    {
        float lg[4], lv[4];
#pragma unroll
        for (int t = 0; t < 4; t++) {
            float4 rv = __ldg((const float4*)g_rv + (t * B_ + b) * HW4_ + i4);
            float m0 = tv.x * rv.x, m1 = tv.y * rv.y, m2 = tv.z * rv.z, m3 = tv.w * rv.w;
            lg[t] = acc0[t].x * m0 + acc0[t].y * m1 + acc0[t].z * m2 + acc0[t].w * m3;
            lv[t] = m0 + m1 + m2 + m3;
        }
#pragma unroll
        for (int o = 16; o > 0; o >>= 1) {
#pragma unroll
            for (int t = 0; t < 4; t++) {
                lg[t] += __shfl_down_sync(0xffffffffu, lg[t], o);
                lv[t] += __shfl_down_sync(0xffffffffu, lv[t], o);
            }
        }
        if (lane == 0) {
#pragma unroll
            for (int t = 0; t < 4; t++) { sg[w][t] = lg[t]; sv[w][t] = lv[t]; }
        }
        __syncthreads();
        if (tid < 4) {
            int tb = tid * B_ + b;
            float a = 0.f, v = 0.f;
#pragma unroll
            for (int i = 0; i < 8; i++) { a += sg[i][tid]; v += sv[i][tid]; }
            g_pgs[tb * NSLOT + px * 16 + chunk] = a;
            if (chunk == 0) g_pvs[tb * NPV + px] = v;
        }
        __syncthreads();
    }

    // ---- h=1: c-loop + mask + partials ----
    {
        const float4* rf = vals4 + ((size_t)(B_ + 4 * B_ + b) * C_ + c0) * HW4_ + i4;
        float4 acc[4];
#pragma unroll
        for (int t = 0; t < 4; t++) acc[t] = make_float4(0.f, 0.f, 0.f, 0.f);
#pragma unroll
        for (int c = 0; c < 8; c++) {
            float4 a = __ldg(tf + c * HW4_);         // L1-resident from h=0
#pragma unroll
            for (int t = 0; t < 4; t++) {
                float4 r = __ldcg(rf + t * tstride + c * HW4_);
                acc[t].x += a.x * r.x; acc[t].y += a.y * r.y;
                acc[t].z += a.z * r.z; acc[t].w += a.w * r.w;
            }
        }

        float lg[4], lv[4];
#pragma unroll
        for (int t = 0; t < 4; t++) {
            float4 rv = __ldg((const float4*)g_rv + ((4 + t) * B_ + b) * HW4_ + i4);
            float m0 = tv.x * rv.x, m1 = tv.y * rv.y, m2 = tv.z * rv.z, m3 = tv.w * rv.w;
            lg[t] = acc[t].x * m0 + acc[t].y * m1 + acc[t].z * m2 + acc[t].w * m3;
            lv[t] = m0 + m1 + m2 + m3;
        }
#pragma unroll
        for (int o = 16; o > 0; o >>= 1) {
#pragma unroll
            for (int t = 0; t < 4; t++) {
                lg[t] += __shfl_down_sync(0xffffffffu, lg[t], o);
                lv[t] += __shfl_down_sync(0xffffffffu, lv[t], o);
            }
        }
        if (lane == 0) {
#pragma unroll
            for (int t = 0; t < 4; t++) { sg[w][t] = lg[t]; sv[w][t] = lv[t]; }
        }
        __syncthreads();
        if (tid < 4) {
            int tb = (4 + tid) * B_ + b;
            float a = 0.f, v = 0.f;
#pragma unroll
            for (int i = 0; i < 8; i++) { a += sg[i][tid]; v += sv[i][tid]; }
            g_pgs[tb * NSLOT + px * 16 + chunk] = a;
            if (chunk == 0) g_pvs[tb * NPV + px] = v;
        }
        __syncthreads();
    }

    // barrier 2: all partials written -> phase B reads
    grid_barrier(tid);

    // ============== phase B: gs finalize + match + aggregate ==============
    __shared__ float sE[T_];
    if (tid < 128) {
        int t = tid >> 4, j = tid & 15;
        int tb = t * B_ + b;
        float s = 0.f;
#pragma unroll
        for (int k = 0; k < 9; k++) s += g_pgs[tb * NSLOT + k * 16 + j];
#pragma unroll
        for (int o = 8; o > 0; o >>= 1)
            s += __shfl_down_sync(0xffffffffu, s, o, 16);
        if (j == 0) {
            float vs = 0.f;
#pragma unroll
            for (int k = 0; k < NPV; k++) vs += g_pvs[tb * NPV + k];
            float g = (vs < 1e-4f) ? 0.f : (s / vs) * (1.f / 128.f);
            sE[t] = expf(g);
            if (px == 0 && chunk == 0)
                d_out[(size_t)B_ * 257 * HW_ + (size_t)B_ * HW_ + tb] = g;
        }
    }
    __syncthreads();

    const float4* rvp = (const float4*)g_rv + (size_t)b * HW4_ + i4;
    const size_t rvstride = (size_t)B_ * HW4_;

    float4 ms = make_float4(0.f, 0.f, 0.f, 0.f);
    float4 inv;
#pragma unroll
    for (int gi = 0; gi < 2; gi++) {      // reverse of phase-A order: grp1 first
        int grp = 1 - gi;
        int cc0 = c0 + grp * 4;
        const float4* rfb = vals4 + ((size_t)(B_ + b) * C_ + cc0) * HW4_ + i4;

        float4 a0 = make_float4(0.f, 0.f, 0.f, 0.f);
        float4 a1 = a0, a2 = a0, a3 = a0;
#pragma unroll
        for (int t = T_ - 1; t >= 0; t--) {   // newest L2 lines first
            float4 rv = __ldg(rvp + t * rvstride);
            float e = sE[t];
            float4 w4 = make_float4(rv.x * e, rv.y * e, rv.z * e, rv.w * e);
            if (gi == 0) { ms.x += w4.x; ms.y += w4.y; ms.z += w4.z; ms.w += w4.w; }
            float4 r0 = __ldcs(rfb + t * tstride + 0 * HW4_);
            float4 r1 = __ldcs(rfb + t * tstride + 1 * HW4_);
            float4 r2 = __ldcs(rfb + t * tstride + 2 * HW4_);
            float4 r3 = __ldcs(rfb + t * tstride + 3 * HW4_);
            a0.x += r0.x * w4.x; a0.y += r0.y * w4.y; a0.z += r0.z * w4.z; a0.w += r0.w * w4.w;
            a1.x += r1.x * w4.x; a1.y += r1.y * w4.y; a1.z += r1.z * w4.z; a1.w += r1.w * w4.w;
            a2.x += r2.x * w4.x; a2.y += r2.y * w4.y; a2.z += r2.z * w4.z; a2.w += r2.w * w4.w;
            a3.x += r3.x * w4.x; a3.y += r3.y * w4.y; a3.z += r3.z * w4.z; a3.w += r3.w * w4.w;
        }

        if (gi == 0) {
            inv.x = 1.f / (ms.x + ((ms.x < 1e-4f) ? 1.f : 0.f));
            inv.y = 1.f / (ms.y + ((ms.y < 1e-4f) ? 1.f : 0.f));
            inv.z = 1.f / (ms.z + ((ms.z < 1e-4f) ? 1.f : 0.f));
            inv.w = 1.f / (ms.w + ((ms.w < 1e-4f) ? 1.f : 0.f));
            if (chunk == 0) {   // c_mask written once per pixel
                float4 msk = make_float4(1.f - ms.x * inv.x, 1.f - ms.y * inv.y,
                                         1.f - ms.z * inv.z, 1.f - ms.w * inv.w);
                float4* op = (float4*)d_out;
                __stcs(&op[((size_t)b * 257 + 256) * HW4_ + i4], msk);
                __stcs(&op[(size_t)B_ * 257 * HW4_ + (size_t)b * HW4_ + i4], msk);
            }
        }

        a0.x *= inv.x; a0.y *= inv.y; a0.z *= inv.z; a0.w *= inv.w;
        a1.x *= inv.x; a1.y *= inv.y; a1.z *= inv.z; a1.w *= inv.w;
        a2.x *= inv.x; a2.y *= inv.y; a2.z *= inv.z; a2.w *= inv.w;
        a3.x *= inv.x; a3.y *= inv.y; a3.z *= inv.z; a3.w *= inv.w;

        float4* outc = (float4*)d_out + ((size_t)b * 257 + 128 + cc0) * HW4_ + i4;
        __stcs(&outc[0 * HW4_], a0);
        __stcs(&outc[1 * HW4_], a1);
        __stcs(&outc[2 * HW4_], a2);
        __stcs(&outc[3 * HW4_], a3);
    }
}

// ---------------------------------------------------------------------------
extern "C" void kernel_launch(void* const* d_in, const int* in_sizes, int n_in,
                              void* d_out, int out_size) {
    const float* values = (const float*)d_in[0];   // (9,4,128,96,96)
    const float* tvmap  = (const float*)d_in[1];   // (4,1,384,384)
    const float* rvmaps = (const float*)d_in[2];   // (8,4,1,384,384)
    float* out = (float*)d_out;

    dim3 gf(9, 16, B_);
    fused_kernel<<<gf, 256>>>(values, tvmap, rvmaps, out);
}

// round 13
// speedup vs baseline: 1.2957x; 1.0314x over previous
#include <cuda_runtime.h>

#define T_ 8
#define B_ 4
#define C_ 128
#define HW_ 9216      // 96*96
#define HW4_ 2304     // HW_/4
#define NTB 32        // T*B
#define GRIDB_ 144    // blocks per batch group: 9 px-tiles * 16 c-chunks
#define NSLOT 144     // partial slots per tb: 9 px * 16 c-chunks
#define NPV 9         // vsum partials per tb

// scratch (static __device__ — no allocation)
__device__ float g_tv[B_ * HW_];
__device__ float g_rv[NTB * HW_];
__device__ float g_pgs[NTB * NSLOT];
__device__ float g_pvs[NTB * NPV];
__device__ unsigned int g_barb[B_];   // per-b cumulative ticket barriers

__device__ __forceinline__ void b_barrier(int tid, int b) {
    __threadfence();
    __syncthreads();
    if (tid == 0) {
        unsigned int ticket = atomicAdd(&g_barb[b], 1u);
        unsigned int target = (ticket / GRIDB_ + 1u) * GRIDB_;
        while (*((volatile unsigned int*)&g_barb[b]) < target) __nanosleep(64);
    }
    __syncthreads();
    __threadfence();
}

// ---------------------------------------------------------------------------
// SINGLE persistent kernel, per-batch decoupled pipelines:
//   phase 0: resize of THIS b's 9 maps (144 blocks per b)
//   h=0 c-loop (streaming hides resize skew)
//   PER-B BARRIER 1 → masks valid
//   h=0 partials, h=1 c-loop + partials
//   PER-B BARRIER 2 → gs valid
//   phase B: gs finalize + match + aggregate
// grid = (9 px, 16 c-chunks of 8, 4 b) = 576 blocks; launch_bounds(256,4)
// guarantees 592 co-resident slots >= 576 (no barrier deadlock).
// ---------------------------------------------------------------------------
__global__ void __launch_bounds__(256, 4) fused_kernel(const float* __restrict__ values,
                                                       const float* __restrict__ tvmap,
                                                       const float* __restrict__ rvmaps,
                                                       float* __restrict__ d_out) {
    int px = blockIdx.x;
    int chunk = blockIdx.y;
    int b = blockIdx.z;
    int c0 = chunk * 8;
    int tid = threadIdx.x;
    int i4 = px * 256 + tid;          // 0..2303

    // ====== phase 0: resize this b's 9 maps (tv[b], rv[t,b] t=0..7) ======
    {
        int rb = px + 9 * chunk;      // 0..143 within b-group
        const float wtab[8] = {1.f, 3.f, 5.f, 7.f, 7.f, 5.f, 3.f, 1.f};
#pragma unroll
        for (int it = 0; it < 3; it++) {
            int idx = rb * 256 + tid + it * (GRIDB_ * 256);
            if (idx >= 9 * HW_) break;
            int ml = idx / HW_;        // 0 = tv, 1..8 = rv[t=ml-1]
            int p = idx - ml * HW_;
            int oy = p / 96, ox = p - oy * 96;

            const float* src = (ml == 0) ? (tvmap + (size_t)b * 147456)
                                         : (rvmaps + (size_t)((ml - 1) * B_ + b) * 147456);
            int iy0 = 4 * oy - 2;
            int xbase = 4 * ox - 4;               // float4-aligned window start
            bool has0 = (ox > 0), has2 = (ox < 95);
            float wxs = 32.f - (has0 ? 0.f : 4.f) - (has2 ? 0.f : 4.f);

            float acc = 0.f, wys = 0.f;
#pragma unroll
            for (int ky = 0; ky < 8; ky++) {
                int iy = iy0 + ky;
                if (iy < 0 || iy >= 384) continue;
                wys += wtab[ky];
                const float4* rp = (const float4*)(src + iy * 384 + xbase);
                float4 b0 = has0 ? __ldg(rp)     : make_float4(0.f, 0.f, 0.f, 0.f);
                float4 b1 = __ldg(rp + 1);
                float4 b2 = has2 ? __ldg(rp + 2) : make_float4(0.f, 0.f, 0.f, 0.f);
                float ra = b0.z + 3.f * b0.w
                         + 5.f * b1.x + 7.f * (b1.y + b1.z) + 5.f * b1.w
                         + 3.f * b2.x + b2.y;
                acc += wtab[ky] * ra;
            }
            float val = acc / (wys * wxs);
            float bin = (val > 0.5f) ? 1.f : 0.f;
            if (ml == 0) g_tv[b * HW_ + p] = bin;
            else         g_rv[((ml - 1) * B_ + b) * HW_ + p] = bin;
        }
    }

    // ============ phase A, half h=0: c-loop (masks NOT needed yet) ==========
    const float4* vals4 = (const float4*)values;
    const float4* tf = vals4 + ((size_t)b * C_ + c0) * HW4_ + i4;
    float4* outp = (float4*)d_out + ((size_t)b * 257 + c0) * HW4_ + i4;
    const size_t tstride = (size_t)B_ * C_ * HW4_;

    __shared__ float sg[8][4], sv[8][4];
    int lane = tid & 31, w = tid >> 5;

    float4 acc0[4];
#pragma unroll
    for (int t = 0; t < 4; t++) acc0[t] = make_float4(0.f, 0.f, 0.f, 0.f);
    {
        const float4* rf = vals4 + ((size_t)(B_ + b) * C_ + c0) * HW4_ + i4;
#pragma unroll
        for (int c = 0; c < 8; c++) {
            float4 a = __ldg(tf + c * HW4_);
            __stcs(&outp[c * HW4_], a);              // t_feat passthrough
#pragma unroll
            for (int t = 0; t < 4; t++) {
                float4 r = __ldcg(rf + t * tstride + c * HW4_);
                acc0[t].x += a.x * r.x; acc0[t].y += a.y * r.y;
                acc0[t].z += a.z * r.z; acc0[t].w += a.w * r.w;
            }
        }
    }

    // per-b barrier 1: this b's resize writes -> this b's mask reads
    b_barrier(tid, b);

    float4 tv = ((const float4*)g_tv)[b * HW4_ + i4];

    // ---- h=0 mask application + partial reduction ----
    {
        float lg[4], lv[4];
#pragma unroll
        for (int t = 0; t < 4; t++) {
            float4 rv = __ldg((const float4*)g_rv + (t * B_ + b) * HW4_ + i4);
            float m0 = tv.x * rv.x, m1 = tv.y * rv.y, m2 = tv.z * rv.z, m3 = tv.w * rv.w;
            lg[t] = acc0[t].x * m0 + acc0[t].y * m1 + acc0[t].z * m2 + acc0[t].w * m3;
            lv[t] = m0 + m1 + m2 + m3;
        }
#pragma unroll
        for (int o = 16; o > 0; o >>= 1) {
#pragma unroll
            for (int t = 0; t < 4; t++) {
                lg[t] += __shfl_down_sync(0xffffffffu, lg[t], o);
                lv[t] += __shfl_down_sync(0xffffffffu, lv[t], o);
            }
        }
        if (lane == 0) {
#pragma unroll
            for (int t = 0; t < 4; t++) { sg[w][t] = lg[t]; sv[w][t] = lv[t]; }
        }
        __syncthreads();
        if (tid < 4) {
            int tb = tid * B_ + b;
            float a = 0.f, v = 0.f;
#pragma unroll
            for (int i = 0; i < 8; i++) { a += sg[i][tid]; v += sv[i][tid]; }
            g_pgs[tb * NSLOT + px * 16 + chunk] = a;
            if (chunk == 0) g_pvs[tb * NPV + px] = v;
        }
        __syncthreads();
    }

    // ---- h=1: c-loop + mask + partials ----
    {
        const float4* rf = vals4 + ((size_t)(B_ + 4 * B_ + b) * C_ + c0) * HW4_ + i4;
        float4 acc[4];
#pragma unroll
        for (int t = 0; t < 4; t++) acc[t] = make_float4(0.f, 0.f, 0.f, 0.f);
#pragma unroll
        for (int c = 0; c < 8; c++) {
            float4 a = __ldg(tf + c * HW4_);         // L1-resident from h=0
#pragma unroll
            for (int t = 0; t < 4; t++) {
                float4 r = __ldcg(rf + t * tstride + c * HW4_);
                acc[t].x += a.x * r.x; acc[t].y += a.y * r.y;
                acc[t].z += a.z * r.z; acc[t].w += a.w * r.w;
            }
        }

        float lg[4], lv[4];
#pragma unroll
        for (int t = 0; t < 4; t++) {
            float4 rv = __ldg((const float4*)g_rv + ((4 + t) * B_ + b) * HW4_ + i4);
            float m0 = tv.x * rv.x, m1 = tv.y * rv.y, m2 = tv.z * rv.z, m3 = tv.w * rv.w;
            lg[t] = acc[t].x * m0 + acc[t].y * m1 + acc[t].z * m2 + acc[t].w * m3;
            lv[t] = m0 + m1 + m2 + m3;
        }
#pragma unroll
        for (int o = 16; o > 0; o >>= 1) {
#pragma unroll
            for (int t = 0; t < 4; t++) {
                lg[t] += __shfl_down_sync(0xffffffffu, lg[t], o);
                lv[t] += __shfl_down_sync(0xffffffffu, lv[t], o);
            }
        }
        if (lane == 0) {
#pragma unroll
            for (int t = 0; t < 4; t++) { sg[w][t] = lg[t]; sv[w][t] = lv[t]; }
        }
        __syncthreads();
        if (tid < 4) {
            int tb = (4 + tid) * B_ + b;
            float a = 0.f, v = 0.f;
#pragma unroll
            for (int i = 0; i < 8; i++) { a += sg[i][tid]; v += sv[i][tid]; }
            g_pgs[tb * NSLOT + px * 16 + chunk] = a;
            if (chunk == 0) g_pvs[tb * NPV + px] = v;
        }
        __syncthreads();
    }

    // per-b barrier 2: this b's partials -> this b's phase B
    b_barrier(tid, b);

    // ============== phase B: gs finalize + match + aggregate ==============
    __shared__ float sE[T_];
    if (tid < 128) {
        int t = tid >> 4, j = tid & 15;
        int tb = t * B_ + b;
        float s = 0.f;
#pragma unroll
        for (int k = 0; k < 9; k++) s += g_pgs[tb * NSLOT + k * 16 + j];
#pragma unroll
        for (int o = 8; o > 0; o >>= 1)
            s += __shfl_down_sync(0xffffffffu, s, o, 16);
        if (j == 0) {
            float vs = 0.f;
#pragma unroll
            for (int k = 0; k < NPV; k++) vs += g_pvs[tb * NPV + k];
            float g = (vs < 1e-4f) ? 0.f : (s / vs) * (1.f / 128.f);
            sE[t] = expf(g);
            if (px == 0 && chunk == 0)
                d_out[(size_t)B_ * 257 * HW_ + (size_t)B_ * HW_ + tb] = g;
        }
    }
    __syncthreads();

    const float4* rvp = (const float4*)g_rv + (size_t)b * HW4_ + i4;
    const size_t rvstride = (size_t)B_ * HW4_;

    float4 ms = make_float4(0.f, 0.f, 0.f, 0.f);
    float4 inv;
#pragma unroll
    for (int gi = 0; gi < 2; gi++) {      // reverse of phase-A order: grp1 first
        int grp = 1 - gi;
        int cc0 = c0 + grp * 4;
        const float4* rfb = vals4 + ((size_t)(B_ + b) * C_ + cc0) * HW4_ + i4;

        float4 a0 = make_float4(0.f, 0.f, 0.f, 0.f);
        float4 a1 = a0, a2 = a0, a3 = a0;
#pragma unroll
        for (int t = T_ - 1; t >= 0; t--) {   // newest L2 lines first
            float4 rv = __ldg(rvp + t * rvstride);
            float e = sE[t];
            float4 w4 = make_float4(rv.x * e, rv.y * e, rv.z * e, rv.w * e);
            if (gi == 0) { ms.x += w4.x; ms.y += w4.y; ms.z += w4.z; ms.w += w4.w; }
            float4 r0 = __ldcs(rfb + t * tstride + 0 * HW4_);
            float4 r1 = __ldcs(rfb + t * tstride + 1 * HW4_);
            float4 r2 = __ldcs(rfb + t * tstride + 2 * HW4_);
            float4 r3 = __ldcs(rfb + t * tstride + 3 * HW4_);
            a0.x += r0.x * w4.x; a0.y += r0.y * w4.y; a0.z += r0.z * w4.z; a0.w += r0.w * w4.w;
            a1.x += r1.x * w4.x; a1.y += r1.y * w4.y; a1.z += r1.z * w4.z; a1.w += r1.w * w4.w;
            a2.x += r2.x * w4.x; a2.y += r2.y * w4.y; a2.z += r2.z * w4.z; a2.w += r2.w * w4.w;
            a3.x += r3.x * w4.x; a3.y += r3.y * w4.y; a3.z += r3.z * w4.z; a3.w += r3.w * w4.w;
        }

        if (gi == 0) {
            inv.x = 1.f / (ms.x + ((ms.x < 1e-4f) ? 1.f : 0.f));
            inv.y = 1.f / (ms.y + ((ms.y < 1e-4f) ? 1.f : 0.f));
            inv.z = 1.f / (ms.z + ((ms.z < 1e-4f) ? 1.f : 0.f));
            inv.w = 1.f / (ms.w + ((ms.w < 1e-4f) ? 1.f : 0.f));
            if (chunk == 0) {   // c_mask written once per pixel
                float4 msk = make_float4(1.f - ms.x * inv.x, 1.f - ms.y * inv.y,
                                         1.f - ms.z * inv.z, 1.f - ms.w * inv.w);
                float4* op = (float4*)d_out;
                __stcs(&op[((size_t)b * 257 + 256) * HW4_ + i4], msk);
                __stcs(&op[(size_t)B_ * 257 * HW4_ + (size_t)b * HW4_ + i4], msk);
            }
        }

        a0.x *= inv.x; a0.y *= inv.y; a0.z *= inv.z; a0.w *= inv.w;
        a1.x *= inv.x; a1.y *= inv.y; a1.z *= inv.z; a1.w *= inv.w;
        a2.x *= inv.x; a2.y *= inv.y; a2.z *= inv.z; a2.w *= inv.w;
        a3.x *= inv.x; a3.y *= inv.y; a3.z *= inv.z; a3.w *= inv.w;

        float4* outc = (float4*)d_out + ((size_t)b * 257 + 128 + cc0) * HW4_ + i4;
        __stcs(&outc[0 * HW4_], a0);
        __stcs(&outc[1 * HW4_], a1);
        __stcs(&outc[2 * HW4_], a2);
        __stcs(&outc[3 * HW4_], a3);
    }
}

// ---------------------------------------------------------------------------
extern "C" void kernel_launch(void* const* d_in, const int* in_sizes, int n_in,
                              void* d_out, int out_size) {
    const float* values = (const float*)d_in[0];   // (9,4,128,96,96)
    const float* tvmap  = (const float*)d_in[1];   // (4,1,384,384)
    const float* rvmaps = (const float*)d_in[2];   // (8,4,1,384,384)
    float* out = (float*)d_out;

    dim3 gf(9, 16, B_);
    fused_kernel<<<gf, 256>>>(values, tvmap, rvmaps, out);
}

// round 14
// speedup vs baseline: 1.3019x; 1.0049x over previous
#include <cuda_runtime.h>

#define T_ 8
#define B_ 4
#define C_ 128
#define HW_ 9216      // 96*96
#define HW4_ 2304     // HW_/4
#define NTB 32        // T*B
#define GRIDB_ 144    // blocks per batch group: 9 px-tiles * 16 c-chunks
#define NSLOT 144     // partial slots per tb: 9 px * 16 c-chunks
#define NPV 9         // vsum partials per tb

// scratch (static __device__ — no allocation)
__device__ float g_tv[B_ * HW_];
__device__ float g_rv[NTB * HW_];
__device__ float g_pgs[NTB * NSLOT];
__device__ float g_pvs[NTB * NPV];
__device__ unsigned int g_barb[B_];   // per-b cumulative ticket barriers

__device__ __forceinline__ void b_barrier(int tid, int b) {
    __threadfence();
    __syncthreads();
    if (tid == 0) {
        unsigned int ticket = atomicAdd(&g_barb[b], 1u);
        unsigned int target = (ticket / GRIDB_ + 1u) * GRIDB_;
        while (*((volatile unsigned int*)&g_barb[b]) < target) __nanosleep(64);
    }
    __syncthreads();
    __threadfence();
}

// ---------------------------------------------------------------------------
// SINGLE persistent kernel, per-batch pipelines, write-through stores,
// continuous phase-A streaming (deferred h0 reduction), phase-B prefetch.
// grid = (9 px, 16 c-chunks of 8, 4 b) = 576 blocks; launch_bounds(256,4).
// ---------------------------------------------------------------------------
__global__ void __launch_bounds__(256, 4) fused_kernel(const float* __restrict__ values,
                                                       const float* __restrict__ tvmap,
                                                       const float* __restrict__ rvmaps,
                                                       float* __restrict__ d_out) {
    int px = blockIdx.x;
    int chunk = blockIdx.y;
    int b = blockIdx.z;
    int c0 = chunk * 8;
    int tid = threadIdx.x;
    int i4 = px * 256 + tid;          // 0..2303

    // ====== phase 0: resize this b's 9 maps (tv[b], rv[t,b] t=0..7) ======
    {
        int rb = px + 9 * chunk;      // 0..143 within b-group
        const float wtab[8] = {1.f, 3.f, 5.f, 7.f, 7.f, 5.f, 3.f, 1.f};
#pragma unroll
        for (int it = 0; it < 3; it++) {
            int idx = rb * 256 + tid + it * (GRIDB_ * 256);
            if (idx >= 9 * HW_) break;
            int ml = idx / HW_;        // 0 = tv, 1..8 = rv[t=ml-1]
            int p = idx - ml * HW_;
            int oy = p / 96, ox = p - oy * 96;

            const float* src = (ml == 0) ? (tvmap + (size_t)b * 147456)
                                         : (rvmaps + (size_t)((ml - 1) * B_ + b) * 147456);
            int iy0 = 4 * oy - 2;
            int xbase = 4 * ox - 4;               // float4-aligned window start
            bool has0 = (ox > 0), has2 = (ox < 95);
            float wxs = 32.f - (has0 ? 0.f : 4.f) - (has2 ? 0.f : 4.f);

            float acc = 0.f, wys = 0.f;
#pragma unroll
            for (int ky = 0; ky < 8; ky++) {
                int iy = iy0 + ky;
                if (iy < 0 || iy >= 384) continue;
                wys += wtab[ky];
                const float4* rp = (const float4*)(src + iy * 384 + xbase);
                float4 b0 = has0 ? __ldg(rp)     : make_float4(0.f, 0.f, 0.f, 0.f);
                float4 b1 = __ldg(rp + 1);
                float4 b2 = has2 ? __ldg(rp + 2) : make_float4(0.f, 0.f, 0.f, 0.f);
                float ra = b0.z + 3.f * b0.w
                         + 5.f * b1.x + 7.f * (b1.y + b1.z) + 5.f * b1.w
                         + 3.f * b2.x + b2.y;
                acc += wtab[ky] * ra;
            }
            float val = acc / (wys * wxs);
            float bin = (val > 0.5f) ? 1.f : 0.f;
            if (ml == 0) g_tv[b * HW_ + p] = bin;
            else         g_rv[((ml - 1) * B_ + b) * HW_ + p] = bin;
        }
    }

    // ============ phase A, half h=0: c-loop (masks NOT needed yet) ==========
    const float4* vals4 = (const float4*)values;
    const float4* tf = vals4 + ((size_t)b * C_ + c0) * HW4_ + i4;
    float4* outp = (float4*)d_out + ((size_t)b * 257 + c0) * HW4_ + i4;
    const size_t tstride = (size_t)B_ * C_ * HW4_;

    __shared__ float sg[2][8][4], sv[2][8][4];
    int lane = tid & 31, w = tid >> 5;

    float4 acc0[4];
#pragma unroll
    for (int t = 0; t < 4; t++) acc0[t] = make_float4(0.f, 0.f, 0.f, 0.f);
    {
        const float4* rf = vals4 + ((size_t)(B_ + b) * C_ + c0) * HW4_ + i4;
#pragma unroll
        for (int c = 0; c < 8; c++) {
            float4 a = __ldg(tf + c * HW4_);
            __stwt(&outp[c * HW4_], a);              // write-through: no L2 fill
#pragma unroll
            for (int t = 0; t < 4; t++) {
                float4 r = __ldcg(rf + t * tstride + c * HW4_);
                acc0[t].x += a.x * r.x; acc0[t].y += a.y * r.y;
                acc0[t].z += a.z * r.z; acc0[t].w += a.w * r.w;
            }
        }
    }

    // per-b barrier 1: this b's resize writes -> this b's mask reads
    b_barrier(tid, b);

    float4 tv = ((const float4*)g_tv)[b * HW4_ + i4];

    // ---- h=0 mask application (per-thread only; reduction deferred) ----
    float lg0[4], lv0[4];
#pragma unroll
    for (int t = 0; t < 4; t++) {
        float4 rv = __ldg((const float4*)g_rv + (t * B_ + b) * HW4_ + i4);
        float m0 = tv.x * rv.x, m1 = tv.y * rv.y, m2 = tv.z * rv.z, m3 = tv.w * rv.w;
        lg0[t] = acc0[t].x * m0 + acc0[t].y * m1 + acc0[t].z * m2 + acc0[t].w * m3;
        lv0[t] = m0 + m1 + m2 + m3;
    }

    // ---- h=1: c-loop (streaming continues immediately) ----
    float lg1[4], lv1[4];
    {
        const float4* rf = vals4 + ((size_t)(B_ + 4 * B_ + b) * C_ + c0) * HW4_ + i4;
        float4 acc[4];
#pragma unroll
        for (int t = 0; t < 4; t++) acc[t] = make_float4(0.f, 0.f, 0.f, 0.f);
#pragma unroll
        for (int c = 0; c < 8; c++) {
            float4 a = __ldg(tf + c * HW4_);         // L1-resident from h=0
#pragma unroll
            for (int t = 0; t < 4; t++) {
                float4 r = __ldcg(rf + t * tstride + c * HW4_);
                acc[t].x += a.x * r.x; acc[t].y += a.y * r.y;
                acc[t].z += a.z * r.z; acc[t].w += a.w * r.w;
            }
        }
#pragma unroll
        for (int t = 0; t < 4; t++) {
            float4 rv = __ldg((const float4*)g_rv + ((4 + t) * B_ + b) * HW4_ + i4);
            float m0 = tv.x * rv.x, m1 = tv.y * rv.y, m2 = tv.z * rv.z, m3 = tv.w * rv.w;
            lg1[t] = acc[t].x * m0 + acc[t].y * m1 + acc[t].z * m2 + acc[t].w * m3;
            lv1[t] = m0 + m1 + m2 + m3;
        }
    }

    // ---- combined reduction for both halves (one sync) ----
#pragma unroll
    for (int o = 16; o > 0; o >>= 1) {
#pragma unroll
        for (int t = 0; t < 4; t++) {
            lg0[t] += __shfl_down_sync(0xffffffffu, lg0[t], o);
            lv0[t] += __shfl_down_sync(0xffffffffu, lv0[t], o);
            lg1[t] += __shfl_down_sync(0xffffffffu, lg1[t], o);
            lv1[t] += __shfl_down_sync(0xffffffffu, lv1[t], o);
        }
    }
    if (lane == 0) {
#pragma unroll
        for (int t = 0; t < 4; t++) {
            sg[0][w][t] = lg0[t]; sv[0][w][t] = lv0[t];
            sg[1][w][t] = lg1[t]; sv[1][w][t] = lv1[t];
        }
    }
    __syncthreads();
    if (tid < 8) {
        int hh = tid >> 2, t4 = tid & 3;
        int t = hh * 4 + t4;
        int tb = t * B_ + b;
        float a = 0.f, v = 0.f;
#pragma unroll
        for (int i = 0; i < 8; i++) { a += sg[hh][i][t4]; v += sv[hh][i][t4]; }
        g_pgs[tb * NSLOT + px * 16 + chunk] = a;
        if (chunk == 0 && hh == 0) {
            float v1 = 0.f;
#pragma unroll
            for (int i = 0; i < 8; i++) v1 += sv[1][i][t4];
            g_pvs[tb * NPV + px] = v;
            g_pvs[((4 + t4) * B_ + b) * NPV + px] = v1;
        }
    }

    // per-b barrier 2: this b's partials -> this b's phase B
    b_barrier(tid, b);

    // ============== phase B: gs finalize + match + aggregate ==============
    const float4* rvp = (const float4*)g_rv + (size_t)b * HW4_ + i4;
    const size_t rvstride = (size_t)B_ * HW4_;

    // prefetch hottest slab (grp=1, t=7) — independent of E
    const float4* rfb1 = vals4 + ((size_t)(B_ + b) * C_ + c0 + 4) * HW4_ + i4;
    float4 pf_rv = __ldg(rvp + 7 * rvstride);
    float4 pf_r0 = __ldcs(rfb1 + 7 * tstride + 0 * HW4_);
    float4 pf_r1 = __ldcs(rfb1 + 7 * tstride + 1 * HW4_);
    float4 pf_r2 = __ldcs(rfb1 + 7 * tstride + 2 * HW4_);
    float4 pf_r3 = __ldcs(rfb1 + 7 * tstride + 3 * HW4_);

    __shared__ float sE[T_];
    if (tid < 128) {
        int t = tid >> 4, j = tid & 15;
        int tb = t * B_ + b;
        float s = 0.f;
#pragma unroll
        for (int k = 0; k < 9; k++) s += g_pgs[tb * NSLOT + k * 16 + j];
#pragma unroll
        for (int o = 8; o > 0; o >>= 1)
            s += __shfl_down_sync(0xffffffffu, s, o, 16);
        if (j == 0) {
            float vs = 0.f;
#pragma unroll
            for (int k = 0; k < NPV; k++) vs += g_pvs[tb * NPV + k];
            float g = (vs < 1e-4f) ? 0.f : (s / vs) * (1.f / 128.f);
            sE[t] = expf(g);
            if (px == 0 && chunk == 0)
                d_out[(size_t)B_ * 257 * HW_ + (size_t)B_ * HW_ + tb] = g;
        }
    }
    __syncthreads();

    float4 ms = make_float4(0.f, 0.f, 0.f, 0.f);
    float4 inv;
#pragma unroll
    for (int gi = 0; gi < 2; gi++) {      // reverse of phase-A order: grp1 first
        int grp = 1 - gi;
        int cc0 = c0 + grp * 4;
        const float4* rfb = vals4 + ((size_t)(B_ + b) * C_ + cc0) * HW4_ + i4;

        float4 a0 = make_float4(0.f, 0.f, 0.f, 0.f);
        float4 a1 = a0, a2 = a0, a3 = a0;
#pragma unroll
        for (int t = T_ - 1; t >= 0; t--) {   // newest L2 lines first
            float4 rv, r0, r1, r2, r3;
            if (gi == 0 && t == 7) {
                rv = pf_rv; r0 = pf_r0; r1 = pf_r1; r2 = pf_r2; r3 = pf_r3;
            } else {
                rv = __ldg(rvp + t * rvstride);
                r0 = __ldcs(rfb + t * tstride + 0 * HW4_);
                r1 = __ldcs(rfb + t * tstride + 1 * HW4_);
                r2 = __ldcs(rfb + t * tstride + 2 * HW4_);
                r3 = __ldcs(rfb + t * tstride + 3 * HW4_);
            }
            float e = sE[t];
            float4 w4 = make_float4(rv.x * e, rv.y * e, rv.z * e, rv.w * e);
            if (gi == 0) { ms.x += w4.x; ms.y += w4.y; ms.z += w4.z; ms.w += w4.w; }
            a0.x += r0.x * w4.x; a0.y += r0.y * w4.y; a0.z += r0.z * w4.z; a0.w += r0.w * w4.w;
            a1.x += r1.x * w4.x; a1.y += r1.y * w4.y; a1.z += r1.z * w4.z; a1.w += r1.w * w4.w;
            a2.x += r2.x * w4.x; a2.y += r2.y * w4.y; a2.z += r2.z * w4.z; a2.w += r2.w * w4.w;
            a3.x += r3.x * w4.x; a3.y += r3.y * w4.y; a3.z += r3.z * w4.z; a3.w += r3.w * w4.w;
        }

        if (gi == 0) {
            inv.x = 1.f / (ms.x + ((ms.x < 1e-4f) ? 1.f : 0.f));
            inv.y = 1.f / (ms.y + ((ms.y < 1e-4f) ? 1.f : 0.f));
            inv.z = 1.f / (ms.z + ((ms.z < 1e-4f) ? 1.f : 0.f));
            inv.w = 1.f / (ms.w + ((ms.w < 1e-4f) ? 1.f : 0.f));
            if (chunk == 0) {   // c_mask written once per pixel
                float4 msk = make_float4(1.f - ms.x * inv.x, 1.f - ms.y * inv.y,
                                         1.f - ms.z * inv.z, 1.f - ms.w * inv.w);
                float4* op = (float4*)d_out;
                __stwt(&op[((size_t)b * 257 + 256) * HW4_ + i4], msk);
                __stwt(&op[(size_t)B_ * 257 * HW4_ + (size_t)b * HW4_ + i4], msk);
            }
        }

        a0.x *= inv.x; a0.y *= inv.y; a0.z *= inv.z; a0.w *= inv.w;
        a1.x *= inv.x; a1.y *= inv.y; a1.z *= inv.z; a1.w *= inv.w;
        a2.x *= inv.x; a2.y *= inv.y; a2.z *= inv.z; a2.w *= inv.w;
        a3.x *= inv.x; a3.y *= inv.y; a3.z *= inv.z; a3.w *= inv.w;

        float4* outc = (float4*)d_out + ((size_t)b * 257 + 128 + cc0) * HW4_ + i4;
        __stwt(&outc[0 * HW4_], a0);
        __stwt(&outc[1 * HW4_], a1);
        __stwt(&outc[2 * HW4_], a2);
        __stwt(&outc[3 * HW4_], a3);
    }
}

// ---------------------------------------------------------------------------
extern "C" void kernel_launch(void* const* d_in, const int* in_sizes, int n_in,
                              void* d_out, int out_size) {
    const float* values = (const float*)d_in[0];   // (9,4,128,96,96)
    const float* tvmap  = (const float*)d_in[1];   // (4,1,384,384)
    const float* rvmaps = (const float*)d_in[2];   // (8,4,1,384,384)
    float* out = (float*)d_out;

    dim3 gf(9, 16, B_);
    fused_kernel<<<gf, 256>>>(values, tvmap, rvmaps, out);
}

// round 15
// speedup vs baseline: 1.3417x; 1.0305x over previous
#include <cuda_runtime.h>

#define T_ 8
#define B_ 4
#define C_ 128
#define HW_ 9216      // 96*96
#define HW4_ 2304     // HW_/4
#define NTB 32        // T*B
#define GRIDB_ 144    // blocks per batch group: 9 px-tiles * 16 c-chunks
#define NSLOT 144     // partial slots per tb: 9 px * 16 c-chunks
#define NPV 9         // vsum partials per tb

// scratch (static __device__ — no allocation)
__device__ float g_tv[B_ * HW_];
__device__ float g_rv[NTB * HW_];
__device__ float g_pgs[NTB * NSLOT];
__device__ float g_pvs[NTB * NPV];
__device__ unsigned int g_barb[B_];   // per-b cumulative ticket barriers

__device__ __forceinline__ void b_barrier(int tid, int b) {
    __threadfence();
    __syncthreads();
    if (tid == 0) {
        unsigned int ticket = atomicAdd(&g_barb[b], 1u);
        unsigned int target = (ticket / GRIDB_ + 1u) * GRIDB_;
        while (*((volatile unsigned int*)&g_barb[b]) < target) __nanosleep(64);
    }
    __syncthreads();
    __threadfence();
}

// ---------------------------------------------------------------------------
// SINGLE persistent kernel, per-batch pipelines, write-through stores,
// t_feat staged in SMEM (read once, zero L2 pollution), phase-B prefetch.
// grid = (9 px, 16 c-chunks of 8, 4 b) = 576 blocks; launch_bounds(256,4).
// ---------------------------------------------------------------------------
__global__ void __launch_bounds__(256, 4) fused_kernel(const float* __restrict__ values,
                                                       const float* __restrict__ tvmap,
                                                       const float* __restrict__ rvmaps,
                                                       float* __restrict__ d_out) {
    int px = blockIdx.x;
    int chunk = blockIdx.y;
    int b = blockIdx.z;
    int c0 = chunk * 8;
    int tid = threadIdx.x;
    int i4 = px * 256 + tid;          // 0..2303

    __shared__ float4 s_tf[8 * 256];  // per-thread tf stash (no sync needed)

    // ====== phase 0: resize this b's 9 maps (tv[b], rv[t,b] t=0..7) ======
    {
        int rb = px + 9 * chunk;      // 0..143 within b-group
        const float wtab[8] = {1.f, 3.f, 5.f, 7.f, 7.f, 5.f, 3.f, 1.f};
#pragma unroll
        for (int it = 0; it < 3; it++) {
            int idx = rb * 256 + tid + it * (GRIDB_ * 256);
            if (idx >= 9 * HW_) break;
            int ml = idx / HW_;        // 0 = tv, 1..8 = rv[t=ml-1]
            int p = idx - ml * HW_;
            int oy = p / 96, ox = p - oy * 96;

            const float* src = (ml == 0) ? (tvmap + (size_t)b * 147456)
                                         : (rvmaps + (size_t)((ml - 1) * B_ + b) * 147456);
            int iy0 = 4 * oy - 2;
            int xbase = 4 * ox - 4;               // float4-aligned window start
            bool has0 = (ox > 0), has2 = (ox < 95);
            float wxs = 32.f - (has0 ? 0.f : 4.f) - (has2 ? 0.f : 4.f);

            float acc = 0.f, wys = 0.f;
#pragma unroll
            for (int ky = 0; ky < 8; ky++) {
                int iy = iy0 + ky;
                if (iy < 0 || iy >= 384) continue;
                wys += wtab[ky];
                const float4* rp = (const float4*)(src + iy * 384 + xbase);
                float4 b0 = has0 ? __ldcs(rp)     : make_float4(0.f, 0.f, 0.f, 0.f);
                float4 b1 = __ldcs(rp + 1);
                float4 b2 = has2 ? __ldcs(rp + 2) : make_float4(0.f, 0.f, 0.f, 0.f);
                float ra = b0.z + 3.f * b0.w
                         + 5.f * b1.x + 7.f * (b1.y + b1.z) + 5.f * b1.w
                         + 3.f * b2.x + b2.y;
                acc += wtab[ky] * ra;
            }
            float val = acc / (wys * wxs);
            float bin = (val > 0.5f) ? 1.f : 0.f;
            if (ml == 0) g_tv[b * HW_ + p] = bin;
            else         g_rv[((ml - 1) * B_ + b) * HW_ + p] = bin;
        }
    }

    // ============ phase A, half h=0: c-loop (masks NOT needed yet) ==========
    const float4* vals4 = (const float4*)values;
    const float4* tf = vals4 + ((size_t)b * C_ + c0) * HW4_ + i4;
    float4* outp = (float4*)d_out + ((size_t)b * 257 + c0) * HW4_ + i4;
    const size_t tstride = (size_t)B_ * C_ * HW4_;

    __shared__ float sg[2][8][4], sv[2][8][4];
    int lane = tid & 31, w = tid >> 5;

    float4 acc0[4];
#pragma unroll
    for (int t = 0; t < 4; t++) acc0[t] = make_float4(0.f, 0.f, 0.f, 0.f);
    {
        const float4* rf = vals4 + ((size_t)(B_ + b) * C_ + c0) * HW4_ + i4;
#pragma unroll
        for (int c = 0; c < 8; c++) {
            float4 a = __ldcs(tf + c * HW4_);        // single read, no L2 fill
            s_tf[c * 256 + tid] = a;                 // stash for h=1 (own thread)
            __stwt(&outp[c * HW4_], a);              // write-through: no L2 fill
#pragma unroll
            for (int t = 0; t < 4; t++) {
                float4 r = __ldcg(rf + t * tstride + c * HW4_);
                acc0[t].x += a.x * r.x; acc0[t].y += a.y * r.y;
                acc0[t].z += a.z * r.z; acc0[t].w += a.w * r.w;
            }
        }
    }

    // per-b barrier 1: this b's resize writes -> this b's mask reads
    b_barrier(tid, b);

    float4 tv = ((const float4*)g_tv)[b * HW4_ + i4];

    // ---- h=0 mask application (per-thread only; reduction deferred) ----
    float lg0[4], lv0[4];
#pragma unroll
    for (int t = 0; t < 4; t++) {
        float4 rv = __ldg((const float4*)g_rv + (t * B_ + b) * HW4_ + i4);
        float m0 = tv.x * rv.x, m1 = tv.y * rv.y, m2 = tv.z * rv.z, m3 = tv.w * rv.w;
        lg0[t] = acc0[t].x * m0 + acc0[t].y * m1 + acc0[t].z * m2 + acc0[t].w * m3;
        lv0[t] = m0 + m1 + m2 + m3;
    }

    // ---- h=1: c-loop (tf from SMEM; streaming continues immediately) ----
    float lg1[4], lv1[4];
    {
        const float4* rf = vals4 + ((size_t)(B_ + 4 * B_ + b) * C_ + c0) * HW4_ + i4;
        float4 acc[4];
#pragma unroll
        for (int t = 0; t < 4; t++) acc[t] = make_float4(0.f, 0.f, 0.f, 0.f);
#pragma unroll
        for (int c = 0; c < 8; c++) {
            float4 a = s_tf[c * 256 + tid];          // LDS, no gmem traffic
#pragma unroll
            for (int t = 0; t < 4; t++) {
                float4 r = __ldcg(rf + t * tstride + c * HW4_);
                acc[t].x += a.x * r.x; acc[t].y += a.y * r.y;
                acc[t].z += a.z * r.z; acc[t].w += a.w * r.w;
            }
        }
#pragma unroll
        for (int t = 0; t < 4; t++) {
            float4 rv = __ldg((const float4*)g_rv + ((4 + t) * B_ + b) * HW4_ + i4);
            float m0 = tv.x * rv.x, m1 = tv.y * rv.y, m2 = tv.z * rv.z, m3 = tv.w * rv.w;
            lg1[t] = acc[t].x * m0 + acc[t].y * m1 + acc[t].z * m2 + acc[t].w * m3;
            lv1[t] = m0 + m1 + m2 + m3;
        }
    }

    // ---- combined reduction for both halves (one sync) ----
#pragma unroll
    for (int o = 16; o > 0; o >>= 1) {
#pragma unroll
        for (int t = 0; t < 4; t++) {
            lg0[t] += __shfl_down_sync(0xffffffffu, lg0[t], o);
            lv0[t] += __shfl_down_sync(0xffffffffu, lv0[t], o);
            lg1[t] += __shfl_down_sync(0xffffffffu, lg1[t], o);
            lv1[t] += __shfl_down_sync(0xffffffffu, lv1[t], o);
        }
    }
    if (lane == 0) {
#pragma unroll
        for (int t = 0; t < 4; t++) {
            sg[0][w][t] = lg0[t]; sv[0][w][t] = lv0[t];
            sg[1][w][t] = lg1[t]; sv[1][w][t] = lv1[t];
        }
    }
    __syncthreads();
    if (tid < 8) {
        int hh = tid >> 2, t4 = tid & 3;
        int t = hh * 4 + t4;
        int tb = t * B_ + b;
        float a = 0.f, v = 0.f;
#pragma unroll
        for (int i = 0; i < 8; i++) { a += sg[hh][i][t4]; v += sv[hh][i][t4]; }
        g_pgs[tb * NSLOT + px * 16 + chunk] = a;
        if (chunk == 0 && hh == 0) {
            float v1 = 0.f;
#pragma unroll
            for (int i = 0; i < 8; i++) v1 += sv[1][i][t4];
            g_pvs[tb * NPV + px] = v;
            g_pvs[((4 + t4) * B_ + b) * NPV + px] = v1;
        }
    }

    // per-b barrier 2: this b's partials -> this b's phase B
    b_barrier(tid, b);

    // ============== phase B: gs finalize + match + aggregate ==============
    const float4* rvp = (const float4*)g_rv + (size_t)b * HW4_ + i4;
    const size_t rvstride = (size_t)B_ * HW4_;

    // prefetch hottest slab (grp=1, t=7) — independent of E
    const float4* rfb1 = vals4 + ((size_t)(B_ + b) * C_ + c0 + 4) * HW4_ + i4;
    float4 pf_rv = __ldg(rvp + 7 * rvstride);
    float4 pf_r0 = __ldcs(rfb1 + 7 * tstride + 0 * HW4_);
    float4 pf_r1 = __ldcs(rfb1 + 7 * tstride + 1 * HW4_);
    float4 pf_r2 = __ldcs(rfb1 + 7 * tstride + 2 * HW4_);
    float4 pf_r3 = __ldcs(rfb1 + 7 * tstride + 3 * HW4_);

    __shared__ float sE[T_];
    if (tid < 128) {
        int t = tid >> 4, j = tid & 15;
        int tb = t * B_ + b;
        float s = 0.f;
#pragma unroll
        for (int k = 0; k < 9; k++) s += g_pgs[tb * NSLOT + k * 16 + j];
#pragma unroll
        for (int o = 8; o > 0; o >>= 1)
            s += __shfl_down_sync(0xffffffffu, s, o, 16);
        if (j == 0) {
            float vs = 0.f;
#pragma unroll
            for (int k = 0; k < NPV; k++) vs += g_pvs[tb * NPV + k];
            float g = (vs < 1e-4f) ? 0.f : (s / vs) * (1.f / 128.f);
            sE[t] = expf(g);
            if (px == 0 && chunk == 0)
                d_out[(size_t)B_ * 257 * HW_ + (size_t)B_ * HW_ + tb] = g;
        }
    }
    __syncthreads();

    float4 ms = make_float4(0.f, 0.f, 0.f, 0.f);
    float4 inv;
#pragma unroll
    for (int gi = 0; gi < 2; gi++) {      // reverse of phase-A order: grp1 first
        int grp = 1 - gi;
        int cc0 = c0 + grp * 4;
        const float4* rfb = vals4 + ((size_t)(B_ + b) * C_ + cc0) * HW4_ + i4;

        float4 a0 = make_float4(0.f, 0.f, 0.f, 0.f);
        float4 a1 = a0, a2 = a0, a3 = a0;
#pragma unroll
        for (int t = T_ - 1; t >= 0; t--) {   // newest L2 lines first
            float4 rv, r0, r1, r2, r3;
            if (gi == 0 && t == 7) {
                rv = pf_rv; r0 = pf_r0; r1 = pf_r1; r2 = pf_r2; r3 = pf_r3;
            } else {
                rv = __ldg(rvp + t * rvstride);
                r0 = __ldcs(rfb + t * tstride + 0 * HW4_);
                r1 = __ldcs(rfb + t * tstride + 1 * HW4_);
                r2 = __ldcs(rfb + t * tstride + 2 * HW4_);
                r3 = __ldcs(rfb + t * tstride + 3 * HW4_);
            }
            float e = sE[t];
            float4 w4 = make_float4(rv.x * e, rv.y * e, rv.z * e, rv.w * e);
            if (gi == 0) { ms.x += w4.x; ms.y += w4.y; ms.z += w4.z; ms.w += w4.w; }
            a0.x += r0.x * w4.x; a0.y += r0.y * w4.y; a0.z += r0.z * w4.z; a0.w += r0.w * w4.w;
            a1.x += r1.x * w4.x; a1.y += r1.y * w4.y; a1.z += r1.z * w4.z; a1.w += r1.w * w4.w;
            a2.x += r2.x * w4.x; a2.y += r2.y * w4.y; a2.z += r2.z * w4.z; a2.w += r2.w * w4.w;
            a3.x += r3.x * w4.x; a3.y += r3.y * w4.y; a3.z += r3.z * w4.z; a3.w += r3.w * w4.w;
        }

        if (gi == 0) {
            inv.x = 1.f / (ms.x + ((ms.x < 1e-4f) ? 1.f : 0.f));
            inv.y = 1.f / (ms.y + ((ms.y < 1e-4f) ? 1.f : 0.f));
            inv.z = 1.f / (ms.z + ((ms.z < 1e-4f) ? 1.f : 0.f));
            inv.w = 1.f / (ms.w + ((ms.w < 1e-4f) ? 1.f : 0.f));
            if (chunk == 0) {   // c_mask written once per pixel
                float4 msk = make_float4(1.f - ms.x * inv.x, 1.f - ms.y * inv.y,
                                         1.f - ms.z * inv.z, 1.f - ms.w * inv.w);
                float4* op = (float4*)d_out;
                __stwt(&op[((size_t)b * 257 + 256) * HW4_ + i4], msk);
                __stwt(&op[(size_t)B_ * 257 * HW4_ + (size_t)b * HW4_ + i4], msk);
            }
        }

        a0.x *= inv.x; a0.y *= inv.y; a0.z *= inv.z; a0.w *= inv.w;
        a1.x *= inv.x; a1.y *= inv.y; a1.z *= inv.z; a1.w *= inv.w;
        a2.x *= inv.x; a2.y *= inv.y; a2.z *= inv.z; a2.w *= inv.w;
        a3.x *= inv.x; a3.y *= inv.y; a3.z *= inv.z; a3.w *= inv.w;

        float4* outc = (float4*)d_out + ((size_t)b * 257 + 128 + cc0) * HW4_ + i4;
        __stwt(&outc[0 * HW4_], a0);
        __stwt(&outc[1 * HW4_], a1);
        __stwt(&outc[2 * HW4_], a2);
        __stwt(&outc[3 * HW4_], a3);
    }
}

// ---------------------------------------------------------------------------
extern "C" void kernel_launch(void* const* d_in, const int* in_sizes, int n_in,
                              void* d_out, int out_size) {
    const float* values = (const float*)d_in[0];   // (9,4,128,96,96)
    const float* tvmap  = (const float*)d_in[1];   // (4,1,384,384)
    const float* rvmaps = (const float*)d_in[2];   // (8,4,1,384,384)
    float* out = (float*)d_out;

    dim3 gf(9, 16, B_);
    fused_kernel<<<gf, 256>>>(values, tvmap, rvmaps, out);
}

// round 16
// speedup vs baseline: 1.3505x; 1.0065x over previous
#include <cuda_runtime.h>

#define T_ 8
#define B_ 4
#define C_ 128
#define HW_ 9216      // 96*96
#define HW4_ 2304     // HW_/4
#define NTB 32        // T*B
#define GRIDB_ 144    // blocks per batch group: 9 px-tiles * 16 c-chunks
#define NSLOT 144     // partial slots per tb: 9 px * 16 c-chunks
#define NPV 9         // vsum partials per tb

// scratch (static __device__ — no allocation)
__device__ float g_tv[B_ * HW_];
__device__ float g_rv[NTB * HW_];
__device__ float g_pgs[NTB * NSLOT];
__device__ float g_pvs[NTB * NPV];
__device__ unsigned int g_barb[B_];   // per-b cumulative ticket barriers

__device__ __forceinline__ void b_barrier(int tid, int b) {
    __threadfence();
    __syncthreads();
    if (tid == 0) {
        unsigned int ticket = atomicAdd(&g_barb[b], 1u);
        unsigned int target = (ticket / GRIDB_ + 1u) * GRIDB_;
        while (*((volatile unsigned int*)&g_barb[b]) < target) __nanosleep(64);
    }
    __syncthreads();
    __threadfence();
}

// ---------------------------------------------------------------------------
// SINGLE persistent kernel, per-batch pipelines, write-through stores,
// t_feat staged in SMEM, QUAD-vectorized resize, phase-B prefetch.
// grid = (9 px, 16 c-chunks of 8, 4 b) = 576 blocks; launch_bounds(256,4).
// ---------------------------------------------------------------------------
__global__ void __launch_bounds__(256, 4) fused_kernel(const float* __restrict__ values,
                                                       const float* __restrict__ tvmap,
                                                       const float* __restrict__ rvmaps,
                                                       float* __restrict__ d_out) {
    int px = blockIdx.x;
    int chunk = blockIdx.y;
    int b = blockIdx.z;
    int c0 = chunk * 8;
    int tid = threadIdx.x;
    int i4 = px * 256 + tid;          // 0..2303

    __shared__ float4 s_tf[8 * 256];  // per-thread tf stash (no sync needed)

    // ====== phase 0: resize this b's 9 maps, 4 output px per thread ======
    {
        int rb = px + 9 * chunk;      // 0..143 within b-group
        int q = rb * 256 + tid;       // quad index: 9 maps * 2304 quads
        if (q < 9 * 2304) {
            int ml = q / 2304;        // 0 = tv, 1..8 = rv[t=ml-1]
            int rem = q - ml * 2304;
            int oy = rem / 24;
            int ox0 = (rem - oy * 24) * 4;   // first of 4 output columns

            const float* src = (ml == 0) ? (tvmap + (size_t)b * 147456)
                                         : (rvmaps + (size_t)((ml - 1) * B_ + b) * 147456);
            const float wtab[8] = {1.f, 3.f, 5.f, 7.f, 7.f, 5.f, 3.f, 1.f};
            int iy0 = 4 * oy - 2;
            int xbase = 4 * ox0 - 4;          // aligned window start (24 floats)
            bool has0 = (ox0 > 0);            // first float4 fully in-range?
            bool has5 = (ox0 < 92);           // last float4 fully in-range?

            float acc[4] = {0.f, 0.f, 0.f, 0.f};
            float wys = 0.f;
#pragma unroll
            for (int ky = 0; ky < 8; ky++) {
                int iy = iy0 + ky;
                if (iy < 0 || iy >= 384) continue;
                wys += wtab[ky];
                const float4* rp = (const float4*)(src + iy * 384 + xbase);
                float4 z = make_float4(0.f, 0.f, 0.f, 0.f);
                float4 f0 = has0 ? __ldcs(rp)     : z;
                float4 f1 = __ldcs(rp + 1);
                float4 f2 = __ldcs(rp + 2);
                float4 f3 = __ldcs(rp + 3);
                float4 f4 = __ldcs(rp + 4);
                float4 f5 = has5 ? __ldcs(rp + 5) : z;
                float buf[24] = {f0.x, f0.y, f0.z, f0.w, f1.x, f1.y, f1.z, f1.w,
                                 f2.x, f2.y, f2.z, f2.w, f3.x, f3.y, f3.z, f3.w,
                                 f4.x, f4.y, f4.z, f4.w, f5.x, f5.y, f5.z, f5.w};
                float wk = wtab[ky];
#pragma unroll
                for (int j = 0; j < 4; j++) {
                    float ra = 0.f;
#pragma unroll
                    for (int k = 0; k < 8; k++) ra += wtab[k] * buf[4 * j + 2 + k];
                    acc[j] += wk * ra;
                }
            }
            // per-output horizontal renorm (edge taps clipped exactly)
            float4 bins;
            float wxs0 = (ox0 == 0)  ? 28.f : 32.f;
            float wxs3 = (ox0 == 92) ? 28.f : 32.f;
            bins.x = (acc[0] / (wys * wxs0) > 0.5f) ? 1.f : 0.f;
            bins.y = (acc[1] / (wys * 32.f) > 0.5f) ? 1.f : 0.f;
            bins.z = (acc[2] / (wys * 32.f) > 0.5f) ? 1.f : 0.f;
            bins.w = (acc[3] / (wys * wxs3) > 0.5f) ? 1.f : 0.f;

            int p = oy * 96 + ox0;            // 4-aligned
            if (ml == 0) *(float4*)(g_tv + b * HW_ + p) = bins;
            else         *(float4*)(g_rv + ((ml - 1) * B_ + b) * HW_ + p) = bins;
        }
    }

    // ============ phase A, half h=0: c-loop (masks NOT needed yet) ==========
    const float4* vals4 = (const float4*)values;
    const float4* tf = vals4 + ((size_t)b * C_ + c0) * HW4_ + i4;
    float4* outp = (float4*)d_out + ((size_t)b * 257 + c0) * HW4_ + i4;
    const size_t tstride = (size_t)B_ * C_ * HW4_;

    __shared__ float sg[2][8][4], sv[2][8][4];
    int lane = tid & 31, w = tid >> 5;

    float4 acc0[4];
#pragma unroll
    for (int t = 0; t < 4; t++) acc0[t] = make_float4(0.f, 0.f, 0.f, 0.f);
    {
        const float4* rf = vals4 + ((size_t)(B_ + b) * C_ + c0) * HW4_ + i4;
#pragma unroll
        for (int c = 0; c < 8; c++) {
            float4 a = __ldcs(tf + c * HW4_);        // single read, no L2 fill
            s_tf[c * 256 + tid] = a;                 // stash for h=1 (own thread)
            __stwt(&outp[c * HW4_], a);              // write-through: no L2 fill
#pragma unroll
            for (int t = 0; t < 4; t++) {
                float4 r = __ldcg(rf + t * tstride + c * HW4_);
                acc0[t].x += a.x * r.x; acc0[t].y += a.y * r.y;
                acc0[t].z += a.z * r.z; acc0[t].w += a.w * r.w;
            }
        }
    }

    // per-b barrier 1: this b's resize writes -> this b's mask reads
    b_barrier(tid, b);

    float4 tv = ((const float4*)g_tv)[b * HW4_ + i4];

    // ---- h=0 mask application (per-thread only; reduction deferred) ----
    float lg0[4], lv0[4];
#pragma unroll
    for (int t = 0; t < 4; t++) {
        float4 rv = __ldg((const float4*)g_rv + (t * B_ + b) * HW4_ + i4);
        float m0 = tv.x * rv.x, m1 = tv.y * rv.y, m2 = tv.z * rv.z, m3 = tv.w * rv.w;
        lg0[t] = acc0[t].x * m0 + acc0[t].y * m1 + acc0[t].z * m2 + acc0[t].w * m3;
        lv0[t] = m0 + m1 + m2 + m3;
    }

    // ---- h=1: c-loop (tf from SMEM; streaming continues immediately) ----
    float lg1[4], lv1[4];
    {
        const float4* rf = vals4 + ((size_t)(B_ + 4 * B_ + b) * C_ + c0) * HW4_ + i4;
        float4 acc[4];
#pragma unroll
        for (int t = 0; t < 4; t++) acc[t] = make_float4(0.f, 0.f, 0.f, 0.f);
#pragma unroll
        for (int c = 0; c < 8; c++) {
            float4 a = s_tf[c * 256 + tid];          // LDS, no gmem traffic
#pragma unroll
            for (int t = 0; t < 4; t++) {
                float4 r = __ldcg(rf + t * tstride + c * HW4_);
                acc[t].x += a.x * r.x; acc[t].y += a.y * r.y;
                acc[t].z += a.z * r.z; acc[t].w += a.w * r.w;
            }
        }
#pragma unroll
        for (int t = 0; t < 4; t++) {
            float4 rv = __ldg((const float4*)g_rv + ((4 + t) * B_ + b) * HW4_ + i4);
            float m0 = tv.x * rv.x, m1 = tv.y * rv.y, m2 = tv.z * rv.z, m3 = tv.w * rv.w;
            lg1[t] = acc[t].x * m0 + acc[t].y * m1 + acc[t].z * m2 + acc[t].w * m3;
            lv1[t] = m0 + m1 + m2 + m3;
        }
    }

    // ---- combined reduction for both halves (one sync) ----
#pragma unroll
    for (int o = 16; o > 0; o >>= 1) {
#pragma unroll
        for (int t = 0; t < 4; t++) {
            lg0[t] += __shfl_down_sync(0xffffffffu, lg0[t], o);
            lv0[t] += __shfl_down_sync(0xffffffffu, lv0[t], o);
            lg1[t] += __shfl_down_sync(0xffffffffu, lg1[t], o);
            lv1[t] += __shfl_down_sync(0xffffffffu, lv1[t], o);
        }
    }
    if (lane == 0) {
#pragma unroll
        for (int t = 0; t < 4; t++) {
            sg[0][w][t] = lg0[t]; sv[0][w][t] = lv0[t];
            sg[1][w][t] = lg1[t]; sv[1][w][t] = lv1[t];
        }
    }
    __syncthreads();
    if (tid < 8) {
        int hh = tid >> 2, t4 = tid & 3;
        int t = hh * 4 + t4;
        int tb = t * B_ + b;
        float a = 0.f, v = 0.f;
#pragma unroll
        for (int i = 0; i < 8; i++) { a += sg[hh][i][t4]; v += sv[hh][i][t4]; }
        g_pgs[tb * NSLOT + px * 16 + chunk] = a;
        if (chunk == 0 && hh == 0) {
            float v1 = 0.f;
#pragma unroll
            for (int i = 0; i < 8; i++) v1 += sv[1][i][t4];
            g_pvs[tb * NPV + px] = v;
            g_pvs[((4 + t4) * B_ + b) * NPV + px] = v1;
        }
    }

    // per-b barrier 2: this b's partials -> this b's phase B
    b_barrier(tid, b);

    // ============== phase B: gs finalize + match + aggregate ==============
    const float4* rvp = (const float4*)g_rv + (size_t)b * HW4_ + i4;
    const size_t rvstride = (size_t)B_ * HW4_;

    // prefetch hottest slab (grp=1, t=7) — independent of E
    const float4* rfb1 = vals4 + ((size_t)(B_ + b) * C_ + c0 + 4) * HW4_ + i4;
    float4 pf_rv = __ldg(rvp + 7 * rvstride);
    float4 pf_r0 = __ldcs(rfb1 + 7 * tstride + 0 * HW4_);
    float4 pf_r1 = __ldcs(rfb1 + 7 * tstride + 1 * HW4_);
    float4 pf_r2 = __ldcs(rfb1 + 7 * tstride + 2 * HW4_);
    float4 pf_r3 = __ldcs(rfb1 + 7 * tstride + 3 * HW4_);

    __shared__ float sE[T_];
    if (tid < 128) {
        int t = tid >> 4, j = tid & 15;
        int tb = t * B_ + b;
        float s = 0.f;
#pragma unroll
        for (int k = 0; k < 9; k++) s += g_pgs[tb * NSLOT + k * 16 + j];
#pragma unroll
        for (int o = 8; o > 0; o >>= 1)
            s += __shfl_down_sync(0xffffffffu, s, o, 16);
        if (j == 0) {
            float vs = 0.f;
#pragma unroll
            for (int k = 0; k < NPV; k++) vs += g_pvs[tb * NPV + k];
            float g = (vs < 1e-4f) ? 0.f : (s / vs) * (1.f / 128.f);
            sE[t] = expf(g);
            if (px == 0 && chunk == 0)
                d_out[(size_t)B_ * 257 * HW_ + (size_t)B_ * HW_ + tb] = g;
        }
    }
    __syncthreads();

    float4 ms = make_float4(0.f, 0.f, 0.f, 0.f);
    float4 inv;
#pragma unroll
    for (int gi = 0; gi < 2; gi++) {      // reverse of phase-A order: grp1 first
        int grp = 1 - gi;
        int cc0 = c0 + grp * 4;
        const float4* rfb = vals4 + ((size_t)(B_ + b) * C_ + cc0) * HW4_ + i4;

        float4 a0 = make_float4(0.f, 0.f, 0.f, 0.f);
        float4 a1 = a0, a2 = a0, a3 = a0;
#pragma unroll
        for (int t = T_ - 1; t >= 0; t--) {   // newest L2 lines first
            float4 rv, r0, r1, r2, r3;
            if (gi == 0 && t == 7) {
                rv = pf_rv; r0 = pf_r0; r1 = pf_r1; r2 = pf_r2; r3 = pf_r3;
            } else {
                rv = __ldg(rvp + t * rvstride);
                r0 = __ldcs(rfb + t * tstride + 0 * HW4_);
                r1 = __ldcs(rfb + t * tstride + 1 * HW4_);
                r2 = __ldcs(rfb + t * tstride + 2 * HW4_);
                r3 = __ldcs(rfb + t * tstride + 3 * HW4_);
            }
            float e = sE[t];
            float4 w4 = make_float4(rv.x * e, rv.y * e, rv.z * e, rv.w * e);
            if (gi == 0) { ms.x += w4.x; ms.y += w4.y; ms.z += w4.z; ms.w += w4.w; }
            a0.x += r0.x * w4.x; a0.y += r0.y * w4.y; a0.z += r0.z * w4.z; a0.w += r0.w * w4.w;
            a1.x += r1.x * w4.x; a1.y += r1.y * w4.y; a1.z += r1.z * w4.z; a1.w += r1.w * w4.w;
            a2.x += r2.x * w4.x; a2.y += r2.y * w4.y; a2.z += r2.z * w4.z; a2.w += r2.w * w4.w;
            a3.x += r3.x * w4.x; a3.y += r3.y * w4.y; a3.z += r3.z * w4.z; a3.w += r3.w * w4.w;
        }

        if (gi == 0) {
            inv.x = 1.f / (ms.x + ((ms.x < 1e-4f) ? 1.f : 0.f));
            inv.y = 1.f / (ms.y + ((ms.y < 1e-4f) ? 1.f : 0.f));
            inv.z = 1.f / (ms.z + ((ms.z < 1e-4f) ? 1.f : 0.f));
            inv.w = 1.f / (ms.w + ((ms.w < 1e-4f) ? 1.f : 0.f));
            if (chunk == 0) {   // c_mask written once per pixel
                float4 msk = make_float4(1.f - ms.x * inv.x, 1.f - ms.y * inv.y,
                                         1.f - ms.z * inv.z, 1.f - ms.w * inv.w);
                float4* op = (float4*)d_out;
                __stwt(&op[((size_t)b * 257 + 256) * HW4_ + i4], msk);
                __stwt(&op[(size_t)B_ * 257 * HW4_ + (size_t)b * HW4_ + i4], msk);
            }
        }

        a0.x *= inv.x; a0.y *= inv.y; a0.z *= inv.z; a0.w *= inv.w;
        a1.x *= inv.x; a1.y *= inv.y; a1.z *= inv.z; a1.w *= inv.w;
        a2.x *= inv.x; a2.y *= inv.y; a2.z *= inv.z; a2.w *= inv.w;
        a3.x *= inv.x; a3.y *= inv.y; a3.z *= inv.z; a3.w *= inv.w;

        float4* outc = (float4*)d_out + ((size_t)b * 257 + 128 + cc0) * HW4_ + i4;
        __stwt(&outc[0 * HW4_], a0);
        __stwt(&outc[1 * HW4_], a1);
        __stwt(&outc[2 * HW4_], a2);
        __stwt(&outc[3 * HW4_], a3);
    }
}

// ---------------------------------------------------------------------------
extern "C" void kernel_launch(void* const* d_in, const int* in_sizes, int n_in,
                              void* d_out, int out_size) {
    const float* values = (const float*)d_in[0];   // (9,4,128,96,96)
    const float* tvmap  = (const float*)d_in[1];   // (4,1,384,384)
    const float* rvmaps = (const float*)d_in[2];   // (8,4,1,384,384)
    float* out = (float*)d_out;

    dim3 gf(9, 16, B_);
    fused_kernel<<<gf, 256>>>(values, tvmap, rvmaps, out);
}